// round 1
// baseline (speedup 1.0000x reference)
#include <cuda_runtime.h>
#include <math.h>

// Problem constants
#define Bc 4
#define Tc 1024
#define Cc 1024
#define Hc 16
#define Dc 64
#define BT (Bc*Tc)          // 4096
#define SINKc 4

// ---------------- scratch (static device memory; no allocations) ----------------
__device__ float g_h  [(size_t)BT*Cc];        // ln1 out, reused as ln2 out
__device__ float g_q  [(size_t)BT*Cc];        // (B,H,T,D)
__device__ float g_k  [(size_t)BT*Cc];
__device__ float g_v  [(size_t)BT*Cc];
__device__ float g_att[(size_t)Bc*Hc*Tc*Tc];  // (B,H,T,T) 256MB
__device__ float g_y  [(size_t)BT*Cc];        // (B,T,C)
__device__ float g_x2 [(size_t)BT*Cc];
__device__ float g_fc [(size_t)BT*4*Cc];      // (BT, 4C)
__device__ float g_part[(size_t)Bc*Hc*16*Tc]; // colsum partials
__device__ float g_imp[BT];

// ---------------- LayerNorm: one block per row of C=1024 ----------------
__global__ void __launch_bounds__(256) ln_kernel(const float* __restrict__ x,
                                                 const float* __restrict__ w,
                                                 const float* __restrict__ b,
                                                 float* __restrict__ out) {
    int row = blockIdx.x;
    const float* xr = x + (size_t)row * Cc;
    float s = 0.f, s2 = 0.f;
    for (int i = threadIdx.x; i < Cc; i += 256) {
        float v = xr[i]; s += v; s2 += v * v;
    }
    #pragma unroll
    for (int o = 16; o; o >>= 1) {
        s  += __shfl_xor_sync(~0u, s,  o);
        s2 += __shfl_xor_sync(~0u, s2, o);
    }
    __shared__ float ws[8], ws2[8];
    int wid = threadIdx.x >> 5, lid = threadIdx.x & 31;
    if (lid == 0) { ws[wid] = s; ws2[wid] = s2; }
    __syncthreads();
    if (threadIdx.x == 0) {
        float a = 0.f, a2 = 0.f;
        #pragma unroll
        for (int i = 0; i < 8; i++) { a += ws[i]; a2 += ws2[i]; }
        ws[0] = a; ws2[0] = a2;
    }
    __syncthreads();
    float mean = ws[0] * (1.0f / Cc);
    float var  = ws2[0] * (1.0f / Cc) - mean * mean;
    float inv  = rsqrtf(var + 1e-5f);
    float* orow = out + (size_t)row * Cc;
    for (int i = threadIdx.x; i < Cc; i += 256)
        orow[i] = (xr[i] - mean) * inv * w[i] + b[i];
}

// ---------------- Generic SGEMM 128x128x8, 256 threads, 8x8 per thread ----------
// EPI: 1 = qkv split-store, 2 = +bias +res -> out, 3 = gelu(+bias) -> out
template<int EPI>
__global__ void __launch_bounds__(256) sgemm_kernel(
    const float* __restrict__ A, const float* __restrict__ Bm,
    const float* __restrict__ bias, const float* __restrict__ res,
    float* __restrict__ out, float* __restrict__ outK, float* __restrict__ outV,
    int M, int N, int K)
{
    __shared__ float As[8][128];
    __shared__ float Bs[8][128];
    int tid = threadIdx.x;
    int bm = blockIdx.y * 128, bn = blockIdx.x * 128;
    int ty = tid >> 4, tx = tid & 15;

    float acc[8][8];
    #pragma unroll
    for (int i = 0; i < 8; i++)
        #pragma unroll
        for (int j = 0; j < 8; j++) acc[i][j] = 0.f;

    int arow = tid >> 1;            // 0..127
    int acol = (tid & 1) * 4;       // 0 or 4
    int brow = tid >> 5;            // 0..7
    int bcol = (tid & 31) * 4;      // 0..124
    const float* Aptr = A + (size_t)(bm + arow) * K + acol;
    const float* Bptr = Bm + (size_t)brow * N + bn + bcol;

    for (int k0 = 0; k0 < K; k0 += 8) {
        float4 av = *(const float4*)Aptr;
        As[acol+0][arow] = av.x; As[acol+1][arow] = av.y;
        As[acol+2][arow] = av.z; As[acol+3][arow] = av.w;
        *(float4*)&Bs[brow][bcol] = *(const float4*)Bptr;
        __syncthreads();
        #pragma unroll
        for (int kk = 0; kk < 8; kk++) {
            float4 a0 = *(const float4*)&As[kk][ty*8];
            float4 a1 = *(const float4*)&As[kk][ty*8+4];
            float4 b0 = *(const float4*)&Bs[kk][tx*8];
            float4 b1 = *(const float4*)&Bs[kk][tx*8+4];
            float ar[8] = {a0.x,a0.y,a0.z,a0.w,a1.x,a1.y,a1.z,a1.w};
            float br[8] = {b0.x,b0.y,b0.z,b0.w,b1.x,b1.y,b1.z,b1.w};
            #pragma unroll
            for (int i = 0; i < 8; i++)
                #pragma unroll
                for (int j = 0; j < 8; j++)
                    acc[i][j] += ar[i] * br[j];
        }
        __syncthreads();
        Aptr += 8;
        Bptr += (size_t)8 * N;
    }

    #pragma unroll
    for (int i = 0; i < 8; i++) {
        int row = bm + ty*8 + i;
        #pragma unroll
        for (int j = 0; j < 8; j++) {
            int col = bn + tx*8 + j;
            float v = acc[i][j] + bias[col];
            if (EPI == 1) {
                int sec = col >> 10;        // 0=q 1=k 2=v
                int wc  = col & 1023;
                int h = wc >> 6, d = wc & 63;
                int bb = row >> 10, t = row & 1023;
                float* dst = (sec == 0) ? out : (sec == 1) ? outK : outV;
                dst[(((size_t)(bb*Hc + h))*Tc + t)*Dc + d] = v;
            } else if (EPI == 2) {
                out[(size_t)row*N + col] = v + res[(size_t)row*N + col];
            } else if (EPI == 3) {
                out[(size_t)row*N + col] = 0.5f * v * (1.0f + erff(v * 0.70710678118f));
            }
        }
    }
}

// ---------------- scores = q @ k^T * 1/sqrt(D), masked ----------------
__global__ void __launch_bounds__(256) scores_kernel(const int* __restrict__ amask) {
    int bh = blockIdx.z;
    int b  = bh >> 4;
    int i0 = blockIdx.y * 64, j0 = blockIdx.x * 64;
    size_t base = (size_t)bh * Tc * Tc;
    int tid = threadIdx.x;
    int ty = tid >> 4, tx = tid & 15;

    if (j0 > i0 + 63) {  // fully above the diagonal: all masked
        #pragma unroll
        for (int i = 0; i < 4; i++) {
            int ig = i0 + ty*4 + i;
            float4 w = make_float4(-1e30f, -1e30f, -1e30f, -1e30f);
            *(float4*)&g_att[base + (size_t)ig*Tc + j0 + tx*4] = w;
        }
        return;
    }

    __shared__ float Qst[64][68];  // [d][row]
    __shared__ float Kst[64][68];  // [d][col]
    const float* qb = g_q + ((size_t)bh*Tc + i0) * Dc;
    const float* kb = g_k + ((size_t)bh*Tc + j0) * Dc;
    #pragma unroll
    for (int r = 0; r < 4; r++) {
        int f = tid + r*256;              // float4 index 0..1023
        int row = f >> 4;
        int c4  = (f & 15) * 4;
        float4 qv = *(const float4*)(qb + (size_t)row*Dc + c4);
        Qst[c4+0][row] = qv.x; Qst[c4+1][row] = qv.y;
        Qst[c4+2][row] = qv.z; Qst[c4+3][row] = qv.w;
        float4 kv = *(const float4*)(kb + (size_t)row*Dc + c4);
        Kst[c4+0][row] = kv.x; Kst[c4+1][row] = kv.y;
        Kst[c4+2][row] = kv.z; Kst[c4+3][row] = kv.w;
    }
    __syncthreads();

    float acc[4][4];
    #pragma unroll
    for (int i = 0; i < 4; i++)
        #pragma unroll
        for (int j = 0; j < 4; j++) acc[i][j] = 0.f;

    #pragma unroll 8
    for (int d = 0; d < 64; d++) {
        float4 q4 = *(const float4*)&Qst[d][ty*4];
        float4 k4 = *(const float4*)&Kst[d][tx*4];
        float qr[4] = {q4.x, q4.y, q4.z, q4.w};
        float kr[4] = {k4.x, k4.y, k4.z, k4.w};
        #pragma unroll
        for (int i = 0; i < 4; i++)
            #pragma unroll
            for (int j = 0; j < 4; j++)
                acc[i][j] += qr[i] * kr[j];
    }

    #pragma unroll
    for (int i = 0; i < 4; i++) {
        int ig = i0 + ty*4 + i;
        #pragma unroll
        for (int j = 0; j < 4; j++) {
            int jg = j0 + tx*4 + j;
            bool keep = (jg <= ig) && (amask[b*Tc + jg] != 0);
            g_att[base + (size_t)ig*Tc + jg] = keep ? acc[i][j] * 0.125f : -1e30f;
        }
    }
}

// ---------------- softmax over rows of length T ----------------
__global__ void __launch_bounds__(256) softmax_kernel() {
    size_t row = blockIdx.x;
    float* p = g_att + row * Tc;
    int tid = threadIdx.x;
    float4 v = *(float4*)(p + tid*4);
    float m = fmaxf(fmaxf(v.x, v.y), fmaxf(v.z, v.w));
    __shared__ float sm[8];
    #pragma unroll
    for (int o = 16; o; o >>= 1) m = fmaxf(m, __shfl_xor_sync(~0u, m, o));
    if ((tid & 31) == 0) sm[tid >> 5] = m;
    __syncthreads();
    if (tid < 8) {
        float t = sm[tid];
        #pragma unroll
        for (int o = 4; o; o >>= 1) t = fmaxf(t, __shfl_xor_sync(0xffu, t, o));
        if (tid == 0) sm[0] = t;
    }
    __syncthreads();
    m = sm[0];
    float4 e;
    e.x = __expf(v.x - m); e.y = __expf(v.y - m);
    e.z = __expf(v.z - m); e.w = __expf(v.w - m);
    float s = e.x + e.y + e.z + e.w;
    __shared__ float ss[8];
    #pragma unroll
    for (int o = 16; o; o >>= 1) s += __shfl_xor_sync(~0u, s, o);
    if ((tid & 31) == 0) ss[tid >> 5] = s;
    __syncthreads();
    if (tid < 8) {
        float t = ss[tid];
        #pragma unroll
        for (int o = 4; o; o >>= 1) t += __shfl_xor_sync(0xffu, t, o);
        if (tid == 0) ss[0] = t;
    }
    __syncthreads();
    float inv = 1.0f / ss[0];
    e.x *= inv; e.y *= inv; e.z *= inv; e.w *= inv;
    *(float4*)(p + tid*4) = e;
}

// ---------------- y = att @ v (per b,h), written to (B,T,C) ----------------
__global__ void __launch_bounds__(256) av_kernel() {
    int bh = blockIdx.y;
    int i0 = blockIdx.x * 64;
    int b = bh >> 4, h = bh & 15;
    __shared__ float As[16][68];  // [k][row]
    __shared__ float Vs[16][68];  // [k][col]
    int tid = threadIdx.x, ty = tid >> 4, tx = tid & 15;
    float acc[4][4];
    #pragma unroll
    for (int i = 0; i < 4; i++)
        #pragma unroll
        for (int j = 0; j < 4; j++) acc[i][j] = 0.f;

    const float* attb = g_att + ((size_t)bh*Tc + i0) * Tc;
    const float* vb   = g_v + (size_t)bh * Tc * Dc;
    int kmax = i0 + 64;   // causal: att[q,k]==0 for k>q
    int arow = tid >> 2, ak4 = (tid & 3) * 4;
    int vrow = tid >> 4, vc4 = (tid & 15) * 4;
    for (int k0 = 0; k0 < kmax; k0 += 16) {
        float4 a = *(const float4*)(attb + (size_t)arow*Tc + k0 + ak4);
        As[ak4+0][arow] = a.x; As[ak4+1][arow] = a.y;
        As[ak4+2][arow] = a.z; As[ak4+3][arow] = a.w;
        *(float4*)&Vs[vrow][vc4] = *(const float4*)(vb + (size_t)(k0 + vrow)*Dc + vc4);
        __syncthreads();
        #pragma unroll
        for (int kk = 0; kk < 16; kk++) {
            float4 a4 = *(const float4*)&As[kk][ty*4];
            float4 v4 = *(const float4*)&Vs[kk][tx*4];
            float ar[4] = {a4.x, a4.y, a4.z, a4.w};
            float vr[4] = {v4.x, v4.y, v4.z, v4.w};
            #pragma unroll
            for (int i = 0; i < 4; i++)
                #pragma unroll
                for (int j = 0; j < 4; j++)
                    acc[i][j] += ar[i] * vr[j];
        }
        __syncthreads();
    }
    #pragma unroll
    for (int i = 0; i < 4; i++) {
        size_t rbase = ((size_t)(b*Tc + i0 + ty*4 + i)) * Cc + h*64 + tx*4;
        #pragma unroll
        for (int j = 0; j < 4; j++)
            g_y[rbase + j] = acc[i][j];
    }
}

// ---------------- colsum partials: per (bh, q-chunk) vector over t ----------------
__global__ void __launch_bounds__(256) colsum_kernel() {
    int idx = blockIdx.x;
    int bh = idx >> 4, qc = idx & 15;
    const float* base = g_att + ((size_t)bh*Tc + qc*64) * Tc;
    int tid = threadIdx.x;
    float4 acc = make_float4(0.f, 0.f, 0.f, 0.f);
    for (int q = 0; q < 64; q++) {
        float4 v = *(const float4*)(base + (size_t)q*Tc + tid*4);
        acc.x += v.x; acc.y += v.y; acc.z += v.z; acc.w += v.w;
    }
    *(float4*)&g_part[(size_t)idx*Tc + tid*4] = acc;
}

// ---------------- reduce partials -> imp (pre-sink) ----------------
__global__ void __launch_bounds__(256) impreduce_kernel() {
    int gt = blockIdx.x * 256 + threadIdx.x;   // 0..4095
    int b = gt >> 10, t = gt & 1023;
    float s = 0.f;
    const float* p = g_part + (size_t)b * 256 * Tc + t;
    for (int i = 0; i < 256; i++) s += p[(size_t)i * Tc];
    float posn = (float)(Tc - t) / (float)Tc;
    g_imp[gt] = (s / (float)Hc) / (posn + 1e-8f);
}

// ---------------- finalize: max, sinks, mask; write to d_out tail ----------------
__global__ void __launch_bounds__(1024) finalize_kernel(const int* __restrict__ amask,
                                                        const float* __restrict__ thrp,
                                                        float* __restrict__ outp) {
    int tid = threadIdx.x;
    float m = -3.4e38f;
    for (int i = tid; i < BT; i += 1024) m = fmaxf(m, g_imp[i]);
    __shared__ float red[32];
    #pragma unroll
    for (int o = 16; o; o >>= 1) m = fmaxf(m, __shfl_xor_sync(~0u, m, o));
    if ((tid & 31) == 0) red[tid >> 5] = m;
    __syncthreads();
    if (tid < 32) {
        float v = red[tid];
        #pragma unroll
        for (int o = 16; o; o >>= 1) v = fmaxf(v, __shfl_xor_sync(~0u, v, o));
        if (tid == 0) red[0] = v;
    }
    __syncthreads();
    float maxv = red[0];
    float thr = *thrp;
    float* maskp = outp + (size_t)BT * Cc;
    float* impp  = maskp + BT;
    for (int i = tid; i < BT; i += 1024) {
        int t = i & 1023;
        float iv = g_imp[i];
        if (t < SINKc) iv = maxv + 1.0f;
        float mk = (iv >= thr) ? 1.0f : 0.0f;
        if (t < SINKc) mk = 1.0f;
        if (amask[i] == 0) mk = 0.0f;
        maskp[i] = mk;
        impp[i]  = iv;
    }
}

// ---------------- launch ----------------
extern "C" void kernel_launch(void* const* d_in, const int* in_sizes, int n_in,
                              void* d_out, int out_size) {
    (void)in_sizes; (void)n_in; (void)out_size;
    const float* x      = (const float*)d_in[0];
    const int*   amask  = (const int*)  d_in[1];
    const float* W_attn = (const float*)d_in[2];
    const float* b_attn = (const float*)d_in[3];
    const float* W_proj = (const float*)d_in[4];
    const float* b_proj = (const float*)d_in[5];
    const float* ln1_w  = (const float*)d_in[6];
    const float* ln1_b  = (const float*)d_in[7];
    const float* ln2_w  = (const float*)d_in[8];
    const float* ln2_b  = (const float*)d_in[9];
    const float* W_fc   = (const float*)d_in[10];
    const float* b_fc   = (const float*)d_in[11];
    const float* W_fc2  = (const float*)d_in[12];
    const float* b_fc2  = (const float*)d_in[13];
    const float* thr    = (const float*)d_in[14];
    float* outp = (float*)d_out;

    float *ph, *pq, *pk, *pv, *py, *px2, *pfc;
    cudaGetSymbolAddress((void**)&ph,  g_h);
    cudaGetSymbolAddress((void**)&pq,  g_q);
    cudaGetSymbolAddress((void**)&pk,  g_k);
    cudaGetSymbolAddress((void**)&pv,  g_v);
    cudaGetSymbolAddress((void**)&py,  g_y);
    cudaGetSymbolAddress((void**)&px2, g_x2);
    cudaGetSymbolAddress((void**)&pfc, g_fc);

    // 1. ln1(x) -> h
    ln_kernel<<<BT, 256>>>(x, ln1_w, ln1_b, ph);
    // 2. qkv = h @ W_attn + b_attn -> q,k,v (B,H,T,D)
    sgemm_kernel<1><<<dim3(3*Cc/128, BT/128), 256>>>(ph, W_attn, b_attn, nullptr,
                                                     pq, pk, pv, BT, 3*Cc, Cc);
    // 3. scores (masked, scaled)
    scores_kernel<<<dim3(Tc/64, Tc/64, Bc*Hc), 256>>>(amask);
    // 4. softmax
    softmax_kernel<<<Bc*Hc*Tc, 256>>>();
    // 5. y = att @ v  -> (B,T,C)
    av_kernel<<<dim3(Tc/64, Bc*Hc), 256>>>();
    // 6-7. importance colsums (deterministic two-stage)
    colsum_kernel<<<Bc*Hc*16, 256>>>();
    impreduce_kernel<<<16, 256>>>();
    // 8. x2 = y @ W_proj + b_proj + x
    sgemm_kernel<2><<<dim3(Cc/128, BT/128), 256>>>(py, W_proj, b_proj, x,
                                                   px2, nullptr, nullptr, BT, Cc, Cc);
    // 9. ln2(x2) -> h (reuse)
    ln_kernel<<<BT, 256>>>(px2, ln2_w, ln2_b, ph);
    // 10. fc = gelu(h @ W_fc + b_fc)
    sgemm_kernel<3><<<dim3(4*Cc/128, BT/128), 256>>>(ph, W_fc, b_fc, nullptr,
                                                     pfc, nullptr, nullptr, BT, 4*Cc, Cc);
    // 11. out = fc @ W_fc2 + b_fc2 + x2  -> d_out head
    sgemm_kernel<2><<<dim3(Cc/128, BT/128), 256>>>(pfc, W_fc2, b_fc2, px2,
                                                   outp, nullptr, nullptr, BT, Cc, 4*Cc);
    // 12. mask + imp tail
    finalize_kernel<<<1, 1024>>>(amask, thr, outp);
}

// round 4
// speedup vs baseline: 1.8949x; 1.8949x over previous
#include <cuda_runtime.h>
#include <cuda_bf16.h>
#include <cstdint>
#include <math.h>

#define Bc 4
#define Tc 1024
#define Cc 1024
#define Hc 16
#define Dc 64
#define BT (Bc*Tc)          // 4096
#define SINKc 4

// ---------------- scratch (fp32 everywhere) ----------------
__device__ float g_h  [(size_t)BT*Cc];        // ln out
__device__ float g_q  [(size_t)BT*Cc];        // (B,H,T,D)
__device__ float g_k  [(size_t)BT*Cc];        // (B,H,T,D)
__device__ float g_vt [(size_t)BT*Cc];        // (B,H,D,T)  transposed V
__device__ float g_y  [(size_t)BT*Cc];        // (B,T,C)
__device__ float g_fc [(size_t)BT*4*Cc];
__device__ float g_x2 [(size_t)BT*Cc];
__device__ float g_att[(size_t)Bc*Hc*Tc*Tc];  // 256MB
__device__ float g_part[(size_t)Bc*Hc*16*Tc];
__device__ float g_imp[BT];
__device__ float g_wat [(size_t)3*Cc*Cc];     // W_attn^T [n][k]
__device__ float g_wpt [(size_t)Cc*Cc];
__device__ float g_wft [(size_t)4*Cc*Cc];
__device__ float g_wf2t[(size_t)Cc*4*Cc];

// ---------------- helpers ----------------
__device__ __forceinline__ uint32_t smem_u32(const void* p) {
    uint32_t r;
    asm("{ .reg .u64 t; cvta.to.shared.u64 t, %1; cvt.u32.u64 %0, t; }"
        : "=r"(r) : "l"(p));
    return r;
}
__device__ __forceinline__ void ldsm4(uint32_t& r0, uint32_t& r1, uint32_t& r2, uint32_t& r3, uint32_t a) {
    asm volatile("ldmatrix.sync.aligned.m8n8.x4.shared.b16 {%0,%1,%2,%3},[%4];"
        : "=r"(r0), "=r"(r1), "=r"(r2), "=r"(r3) : "r"(a));
}
__device__ __forceinline__ void mma_tf32(float* c, uint32_t a0, uint32_t a1, uint32_t a2, uint32_t a3,
                                         uint32_t b0, uint32_t b1) {
    asm volatile("mma.sync.aligned.m16n8k8.row.col.f32.tf32.tf32.f32 "
        "{%0,%1,%2,%3},{%4,%5,%6,%7},{%8,%9},{%0,%1,%2,%3};"
        : "+f"(c[0]), "+f"(c[1]), "+f"(c[2]), "+f"(c[3])
        : "r"(a0), "r"(a1), "r"(a2), "r"(a3), "r"(b0), "r"(b1));
}
__device__ __forceinline__ uint32_t f2tf(float f) {
    uint32_t u;
    asm("cvt.rna.tf32.f32 %0, %1;" : "=r"(u) : "f"(f));
    return u;
}
__device__ __forceinline__ uint4 cvt4(float4 v) {
    uint4 o;
    o.x = f2tf(v.x); o.y = f2tf(v.y); o.z = f2tf(v.z); o.w = f2tf(v.w);
    return o;
}

// ---------------- weight transpose: Wt[n][k] = W[k][n] ----------------
__global__ void __launch_bounds__(256) tr_kernel(const float* __restrict__ W,
                                                 float* __restrict__ Wt, int K, int N) {
    __shared__ float ts[32][33];
    int k0 = blockIdx.y * 32, n0 = blockIdx.x * 32;
    int tx = threadIdx.x & 31, ty = threadIdx.x >> 5;
    #pragma unroll
    for (int i = 0; i < 4; i++) {
        ts[ty + i*8][tx] = W[(size_t)(k0 + ty + i*8) * N + n0 + tx];
    }
    __syncthreads();
    #pragma unroll
    for (int i = 0; i < 4; i++) {
        Wt[(size_t)(n0 + ty + i*8) * K + k0 + tx] = ts[tx][ty + i*8];
    }
}

// ---------------- LayerNorm (fp32 -> fp32), one block per row ----------------
__global__ void __launch_bounds__(256) ln_kernel(const float* __restrict__ x,
                                                 const float* __restrict__ w,
                                                 const float* __restrict__ b,
                                                 float* __restrict__ out) {
    int row = blockIdx.x;
    int tid = threadIdx.x;
    const float* xr = x + (size_t)row * Cc;
    float4 v = *(const float4*)(xr + tid * 4);
    float s  = v.x + v.y + v.z + v.w;
    float s2 = v.x*v.x + v.y*v.y + v.z*v.z + v.w*v.w;
    #pragma unroll
    for (int o = 16; o; o >>= 1) {
        s  += __shfl_xor_sync(~0u, s,  o);
        s2 += __shfl_xor_sync(~0u, s2, o);
    }
    __shared__ float ws[8], ws2[8];
    int wid = tid >> 5, lid = tid & 31;
    if (lid == 0) { ws[wid] = s; ws2[wid] = s2; }
    __syncthreads();
    if (tid < 8) {
        float a = ws[tid], a2 = ws2[tid];
        #pragma unroll
        for (int o = 4; o; o >>= 1) {
            a  += __shfl_xor_sync(0xffu, a,  o);
            a2 += __shfl_xor_sync(0xffu, a2, o);
        }
        if (tid == 0) { ws[0] = a; ws2[0] = a2; }
    }
    __syncthreads();
    float mean = ws[0] * (1.0f / Cc);
    float var  = ws2[0] * (1.0f / Cc) - mean * mean;
    float inv  = rsqrtf(var + 1e-5f);
    int c = tid * 4;
    float4 wv = *(const float4*)(w + c);
    float4 bv = *(const float4*)(b + c);
    float4 ov;
    ov.x = (v.x - mean) * inv * wv.x + bv.x;
    ov.y = (v.y - mean) * inv * wv.y + bv.y;
    ov.z = (v.z - mean) * inv * wv.z + bv.z;
    ov.w = (v.w - mean) * inv * wv.w + bv.w;
    *(float4*)(out + (size_t)row * Cc + c) = ov;
}

// ---------------- tf32 MMA GEMM 128x128x16, 256 threads ----------------
// A: [M][K] row-major fp32.  Bt: [N][K] (pre-transposed weights).
// EPI 1: qkv split (q,k natural; v transposed); EPI 2: +bias+res; EPI 3: gelu
template<int EPI>
__global__ void __launch_bounds__(256, 1) mma_gemm(
    const float* __restrict__ A, const float* __restrict__ Bt,
    const float* __restrict__ bias, const float* __restrict__ res,
    float* __restrict__ outF, float* __restrict__ outQ,
    float* __restrict__ outK, float* __restrict__ outVt,
    int M, int N, int K)
{
    __shared__ float As[2][128][20];
    __shared__ float Bs[2][128][20];
    int tid = threadIdx.x, lane = tid & 31, wid = tid >> 5;
    int wm = wid & 3, wn = wid >> 2;
    int bm = blockIdx.y * 128, bn = blockIdx.x * 128;

    float acc[2][8][4];
    #pragma unroll
    for (int i = 0; i < 2; i++) {
        #pragma unroll
        for (int j = 0; j < 8; j++) {
            #pragma unroll
            for (int k = 0; k < 4; k++) { acc[i][j][k] = 0.f; }
        }
    }

    int row = tid >> 1, kc = (tid & 1) * 8;
    const float* Ap = A  + (size_t)(bm + row) * K + kc;
    const float* Bp = Bt + (size_t)(bn + row) * K + kc;

    // preload tile 0
    {
        float4 a0 = *(const float4*)Ap;
        float4 a1 = *(const float4*)(Ap + 4);
        float4 b0 = *(const float4*)Bp;
        float4 b1 = *(const float4*)(Bp + 4);
        *(uint4*)&As[0][row][kc]     = cvt4(a0);
        *(uint4*)&As[0][row][kc + 4] = cvt4(a1);
        *(uint4*)&Bs[0][row][kc]     = cvt4(b0);
        *(uint4*)&Bs[0][row][kc + 4] = cvt4(b1);
    }
    __syncthreads();

    int cur = 0;
    for (int k0 = 0; k0 < K; k0 += 16) {
        float4 pa0, pa1, pb0, pb1;
        bool more = (k0 + 16) < K;
        if (more) {
            const float* Ap2 = Ap + k0 + 16;
            const float* Bp2 = Bp + k0 + 16;
            pa0 = *(const float4*)Ap2; pa1 = *(const float4*)(Ap2 + 4);
            pb0 = *(const float4*)Bp2; pb1 = *(const float4*)(Bp2 + 4);
        }
        #pragma unroll
        for (int kk = 0; kk < 16; kk += 8) {
            uint32_t af[2][4];
            #pragma unroll
            for (int mt = 0; mt < 2; mt++) {
                ldsm4(af[mt][0], af[mt][1], af[mt][2], af[mt][3],
                      smem_u32(&As[cur][wm*32 + mt*16 + (lane & 15)][kk + (lane >> 4) * 4]));
            }
            uint32_t bfr[8][2];
            #pragma unroll
            for (int np = 0; np < 4; np++) {
                uint32_t r0, r1, r2, r3;
                ldsm4(r0, r1, r2, r3,
                      smem_u32(&Bs[cur][wn*64 + np*16 + (lane & 15)][kk + (lane >> 4) * 4]));
                bfr[np*2][0] = r0;   bfr[np*2][1] = r2;
                bfr[np*2+1][0] = r1; bfr[np*2+1][1] = r3;
            }
            #pragma unroll
            for (int mt = 0; mt < 2; mt++) {
                #pragma unroll
                for (int nt = 0; nt < 8; nt++) {
                    mma_tf32(acc[mt][nt], af[mt][0], af[mt][1], af[mt][2], af[mt][3],
                             bfr[nt][0], bfr[nt][1]);
                }
            }
        }
        if (more) {
            *(uint4*)&As[cur^1][row][kc]     = cvt4(pa0);
            *(uint4*)&As[cur^1][row][kc + 4] = cvt4(pa1);
            *(uint4*)&Bs[cur^1][row][kc]     = cvt4(pb0);
            *(uint4*)&Bs[cur^1][row][kc + 4] = cvt4(pb1);
        }
        __syncthreads();
        cur ^= 1;
    }

    // epilogue
    #pragma unroll
    for (int mt = 0; mt < 2; mt++) {
        #pragma unroll
        for (int nt = 0; nt < 8; nt++) {
            int r0 = bm + wm*32 + mt*16 + (lane >> 2);
            int c0 = bn + wn*64 + nt*8 + (lane & 3) * 2;
            float bb0 = bias[c0], bb1 = bias[c0 + 1];
            #pragma unroll
            for (int rr = 0; rr < 2; rr++) {
                int rg = r0 + rr * 8;
                float v0 = acc[mt][nt][rr*2 + 0] + bb0;
                float v1 = acc[mt][nt][rr*2 + 1] + bb1;
                if (EPI == 1) {
                    int sec = c0 >> 10, wc = c0 & 1023;
                    int h = wc >> 6, d = wc & 63;
                    int bbi = rg >> 10, t = rg & 1023;
                    if (sec == 0) {
                        float2 o; o.x = v0; o.y = v1;
                        *(float2*)&outQ[(((size_t)(bbi*Hc + h))*Tc + t)*Dc + d] = o;
                    } else if (sec == 1) {
                        float2 o; o.x = v0; o.y = v1;
                        *(float2*)&outK[(((size_t)(bbi*Hc + h))*Tc + t)*Dc + d] = o;
                    } else {
                        size_t vb = (((size_t)(bbi*Hc + h))*Dc + d)*Tc + t;
                        outVt[vb] = v0;
                        outVt[vb + Tc] = v1;
                    }
                } else if (EPI == 2) {
                    size_t idx = (size_t)rg * N + c0;
                    float2 rv = *(const float2*)(res + idx);
                    float2 o; o.x = v0 + rv.x; o.y = v1 + rv.y;
                    *(float2*)(outF + idx) = o;
                } else {
                    float g0 = 0.5f * v0 * (1.0f + erff(v0 * 0.70710678118654752f));
                    float g1 = 0.5f * v1 * (1.0f + erff(v1 * 0.70710678118654752f));
                    float2 o; o.x = g0; o.y = g1;
                    *(float2*)&outF[(size_t)rg * N + c0] = o;
                }
            }
        }
    }
}

// ---------------- scores = q@k^T * 1/8, masked -> fp32 g_att (tf32 MMA) ----------------
__global__ void __launch_bounds__(256, 1) scores_mma(const int* __restrict__ amask) {
    int bh = blockIdx.z, b = bh >> 4;
    int i0 = blockIdx.y * 128, j0 = blockIdx.x * 128;
    size_t base = (size_t)bh * Tc * Tc;
    int tid = threadIdx.x, lane = tid & 31, wid = tid >> 5;

    if (j0 >= i0 + 128) {
        float4 m4 = make_float4(-1e30f, -1e30f, -1e30f, -1e30f);
        #pragma unroll
        for (int i = 0; i < 16; i++) {
            int s = tid + i * 256;
            int row = s >> 5, col4 = (s & 31) * 4;
            *(float4*)&g_att[base + (size_t)(i0 + row) * Tc + j0 + col4] = m4;
        }
        return;
    }

    __shared__ float Qs[128][36];
    __shared__ float Ks[128][36];
    int wm = wid & 3, wn = wid >> 2;
    float acc[2][8][4];
    #pragma unroll
    for (int i = 0; i < 2; i++) {
        #pragma unroll
        for (int j = 0; j < 8; j++) {
            #pragma unroll
            for (int k = 0; k < 4; k++) { acc[i][j][k] = 0.f; }
        }
    }

    int row = tid >> 1, kc = (tid & 1) * 16;
    const float* qp = g_q + ((size_t)bh * Tc + i0 + row) * Dc + kc;
    const float* kp = g_k + ((size_t)bh * Tc + j0 + row) * Dc + kc;

    #pragma unroll
    for (int dc = 0; dc < 64; dc += 32) {
        #pragma unroll
        for (int c4 = 0; c4 < 16; c4 += 4) {
            *(uint4*)&Qs[row][kc + c4] = cvt4(*(const float4*)(qp + dc + c4));
            *(uint4*)&Ks[row][kc + c4] = cvt4(*(const float4*)(kp + dc + c4));
        }
        __syncthreads();
        #pragma unroll
        for (int kk = 0; kk < 32; kk += 8) {
            uint32_t af[2][4];
            #pragma unroll
            for (int mt = 0; mt < 2; mt++) {
                ldsm4(af[mt][0], af[mt][1], af[mt][2], af[mt][3],
                      smem_u32(&Qs[wm*32 + mt*16 + (lane & 15)][kk + (lane >> 4) * 4]));
            }
            uint32_t bfr[8][2];
            #pragma unroll
            for (int np = 0; np < 4; np++) {
                uint32_t r0, r1, r2, r3;
                ldsm4(r0, r1, r2, r3,
                      smem_u32(&Ks[wn*64 + np*16 + (lane & 15)][kk + (lane >> 4) * 4]));
                bfr[np*2][0] = r0;   bfr[np*2][1] = r2;
                bfr[np*2+1][0] = r1; bfr[np*2+1][1] = r3;
            }
            #pragma unroll
            for (int mt = 0; mt < 2; mt++) {
                #pragma unroll
                for (int nt = 0; nt < 8; nt++) {
                    mma_tf32(acc[mt][nt], af[mt][0], af[mt][1], af[mt][2], af[mt][3],
                             bfr[nt][0], bfr[nt][1]);
                }
            }
        }
        __syncthreads();
    }

    #pragma unroll
    for (int mt = 0; mt < 2; mt++) {
        #pragma unroll
        for (int nt = 0; nt < 8; nt++) {
            int r0 = i0 + wm*32 + mt*16 + (lane >> 2);
            int c0 = j0 + wn*64 + nt*8 + (lane & 3) * 2;
            int am0 = amask[b * Tc + c0], am1 = amask[b * Tc + c0 + 1];
            #pragma unroll
            for (int rr = 0; rr < 2; rr++) {
                int rg = r0 + rr * 8;
                float s0 = acc[mt][nt][rr*2 + 0] * 0.125f;
                float s1 = acc[mt][nt][rr*2 + 1] * 0.125f;
                float2 ov;
                ov.x = (c0     <= rg && am0) ? s0 : -1e30f;
                ov.y = (c0 + 1 <= rg && am1) ? s1 : -1e30f;
                *(float2*)&g_att[base + (size_t)rg * Tc + c0] = ov;
            }
        }
    }
}

// ---------------- softmax over rows of length T (fp32) ----------------
__global__ void __launch_bounds__(256) softmax_kernel() {
    size_t row = blockIdx.x;
    float* p = g_att + row * Tc;
    int tid = threadIdx.x;
    float4 v = *(float4*)(p + tid * 4);
    float m = fmaxf(fmaxf(v.x, v.y), fmaxf(v.z, v.w));
    __shared__ float sm[8];
    #pragma unroll
    for (int o = 16; o; o >>= 1) { m = fmaxf(m, __shfl_xor_sync(~0u, m, o)); }
    if ((tid & 31) == 0) sm[tid >> 5] = m;
    __syncthreads();
    if (tid < 8) {
        float t = sm[tid];
        #pragma unroll
        for (int o = 4; o; o >>= 1) { t = fmaxf(t, __shfl_xor_sync(0xffu, t, o)); }
        if (tid == 0) sm[0] = t;
    }
    __syncthreads();
    m = sm[0];
    float4 ev;
    ev.x = __expf(v.x - m); ev.y = __expf(v.y - m);
    ev.z = __expf(v.z - m); ev.w = __expf(v.w - m);
    float s = ev.x + ev.y + ev.z + ev.w;
    __shared__ float ssum[8];
    #pragma unroll
    for (int o = 16; o; o >>= 1) { s += __shfl_xor_sync(~0u, s, o); }
    if ((tid & 31) == 0) ssum[tid >> 5] = s;
    __syncthreads();
    if (tid < 8) {
        float t = ssum[tid];
        #pragma unroll
        for (int o = 4; o; o >>= 1) { t += __shfl_xor_sync(0xffu, t, o); }
        if (tid == 0) ssum[0] = t;
    }
    __syncthreads();
    float invs = 1.0f / ssum[0];
    ev.x *= invs; ev.y *= invs; ev.z *= invs; ev.w *= invs;
    *(float4*)(p + tid * 4) = ev;
}

// ---------------- y = att @ v (tf32 MMA) -> g_y (B,T,C) ----------------
__global__ void __launch_bounds__(256, 1) av_mma() {
    int bh = blockIdx.y, b = bh >> 4, h = bh & 15;
    int i0 = blockIdx.x * 128;
    __shared__ float Ps[128][36];
    __shared__ float Vs[64][36];
    int tid = threadIdx.x, lane = tid & 31, wid = tid >> 5;

    float acc[8][4];
    #pragma unroll
    for (int j = 0; j < 8; j++) {
        #pragma unroll
        for (int k = 0; k < 4; k++) { acc[j][k] = 0.f; }
    }

    const float* attp = g_att + ((size_t)bh * Tc + i0) * Tc;
    const float* vtp  = g_vt + (size_t)bh * Dc * Tc;
    int rowp = tid >> 1, kcp = (tid & 1) * 16;
    int rowv = tid >> 2, kcv = (tid & 3) * 8;
    int kmax = i0 + 128;

    for (int k0 = 0; k0 < kmax; k0 += 32) {
        const float* psrc = attp + (size_t)rowp * Tc + k0 + kcp;
        #pragma unroll
        for (int c4 = 0; c4 < 16; c4 += 4) {
            *(uint4*)&Ps[rowp][kcp + c4] = cvt4(*(const float4*)(psrc + c4));
        }
        const float* vsrc = vtp + (size_t)rowv * Tc + k0 + kcv;
        *(uint4*)&Vs[rowv][kcv]     = cvt4(*(const float4*)vsrc);
        *(uint4*)&Vs[rowv][kcv + 4] = cvt4(*(const float4*)(vsrc + 4));
        __syncthreads();
        #pragma unroll
        for (int kk = 0; kk < 32; kk += 8) {
            uint32_t af[4];
            ldsm4(af[0], af[1], af[2], af[3],
                  smem_u32(&Ps[wid*16 + (lane & 15)][kk + (lane >> 4) * 4]));
            uint32_t bfr[8][2];
            #pragma unroll
            for (int np = 0; np < 4; np++) {
                uint32_t r0, r1, r2, r3;
                ldsm4(r0, r1, r2, r3,
                      smem_u32(&Vs[np*16 + (lane & 15)][kk + (lane >> 4) * 4]));
                bfr[np*2][0] = r0;   bfr[np*2][1] = r2;
                bfr[np*2+1][0] = r1; bfr[np*2+1][1] = r3;
            }
            #pragma unroll
            for (int nt = 0; nt < 8; nt++) {
                mma_tf32(acc[nt], af[0], af[1], af[2], af[3], bfr[nt][0], bfr[nt][1]);
            }
        }
        __syncthreads();
    }

    #pragma unroll
    for (int nt = 0; nt < 8; nt++) {
        int q0 = i0 + wid*16 + (lane >> 2);
        int d0 = nt*8 + (lane & 3) * 2;
        #pragma unroll
        for (int rr = 0; rr < 2; rr++) {
            int q = q0 + rr * 8;
            float2 o; o.x = acc[nt][rr*2]; o.y = acc[nt][rr*2 + 1];
            *(float2*)&g_y[(size_t)(b*Tc + q) * Cc + h*64 + d0] = o;
        }
    }
}

// ---------------- colsum partials ----------------
__global__ void __launch_bounds__(256) colsum_kernel() {
    int idx = blockIdx.x;
    int bh = idx >> 4, qc = idx & 15;
    const float* base = g_att + ((size_t)bh * Tc + qc * 64) * Tc;
    int tid = threadIdx.x;
    float4 acc = make_float4(0.f, 0.f, 0.f, 0.f);
    for (int q = 0; q < 64; q++) {
        float4 v = *(const float4*)(base + (size_t)q * Tc + tid * 4);
        acc.x += v.x; acc.y += v.y; acc.z += v.z; acc.w += v.w;
    }
    *(float4*)&g_part[(size_t)idx * Tc + tid * 4] = acc;
}

__global__ void __launch_bounds__(256) impreduce_kernel() {
    int gt = blockIdx.x * 256 + threadIdx.x;
    int b = gt >> 10, t = gt & 1023;
    float s = 0.f;
    const float* p = g_part + (size_t)b * 256 * Tc + t;
    for (int i = 0; i < 256; i++) { s += p[(size_t)i * Tc]; }
    float posn = (float)(Tc - t) / (float)Tc;
    g_imp[gt] = (s / (float)Hc) / (posn + 1e-8f);
}

__global__ void __launch_bounds__(1024) finalize_kernel(const int* __restrict__ amask,
                                                        const float* __restrict__ thrp,
                                                        float* __restrict__ outp) {
    int tid = threadIdx.x;
    float m = -3.4e38f;
    for (int i = tid; i < BT; i += 1024) { m = fmaxf(m, g_imp[i]); }
    __shared__ float red[32];
    #pragma unroll
    for (int o = 16; o; o >>= 1) { m = fmaxf(m, __shfl_xor_sync(~0u, m, o)); }
    if ((tid & 31) == 0) red[tid >> 5] = m;
    __syncthreads();
    if (tid < 32) {
        float v = red[tid];
        #pragma unroll
        for (int o = 16; o; o >>= 1) { v = fmaxf(v, __shfl_xor_sync(~0u, v, o)); }
        if (tid == 0) red[0] = v;
    }
    __syncthreads();
    float maxv = red[0];
    float thr = *thrp;
    float* maskp = outp + (size_t)BT * Cc;
    float* impp  = maskp + BT;
    for (int i = tid; i < BT; i += 1024) {
        int t = i & 1023;
        float iv = g_imp[i];
        if (t < SINKc) iv = maxv + 1.0f;
        float mk = (iv >= thr) ? 1.0f : 0.0f;
        if (t < SINKc) mk = 1.0f;
        if (amask[i] == 0) mk = 0.0f;
        maskp[i] = mk;
        impp[i]  = iv;
    }
}

// ---------------- launch ----------------
extern "C" void kernel_launch(void* const* d_in, const int* in_sizes, int n_in,
                              void* d_out, int out_size) {
    (void)in_sizes; (void)n_in; (void)out_size;
    const float* x      = (const float*)d_in[0];
    const int*   amask  = (const int*)  d_in[1];
    const float* W_attn = (const float*)d_in[2];
    const float* b_attn = (const float*)d_in[3];
    const float* W_proj = (const float*)d_in[4];
    const float* b_proj = (const float*)d_in[5];
    const float* ln1_w  = (const float*)d_in[6];
    const float* ln1_b  = (const float*)d_in[7];
    const float* ln2_w  = (const float*)d_in[8];
    const float* ln2_b  = (const float*)d_in[9];
    const float* W_fc   = (const float*)d_in[10];
    const float* b_fc   = (const float*)d_in[11];
    const float* W_fc2  = (const float*)d_in[12];
    const float* b_fc2  = (const float*)d_in[13];
    const float* thr    = (const float*)d_in[14];
    float* outp = (float*)d_out;

    float *ph, *pq, *pk, *pvt, *py, *pfc, *px2, *pwat, *pwpt, *pwft, *pwf2t;
    cudaGetSymbolAddress((void**)&ph,    g_h);
    cudaGetSymbolAddress((void**)&pq,    g_q);
    cudaGetSymbolAddress((void**)&pk,    g_k);
    cudaGetSymbolAddress((void**)&pvt,   g_vt);
    cudaGetSymbolAddress((void**)&py,    g_y);
    cudaGetSymbolAddress((void**)&pfc,   g_fc);
    cudaGetSymbolAddress((void**)&px2,   g_x2);
    cudaGetSymbolAddress((void**)&pwat,  g_wat);
    cudaGetSymbolAddress((void**)&pwpt,  g_wpt);
    cudaGetSymbolAddress((void**)&pwft,  g_wft);
    cudaGetSymbolAddress((void**)&pwf2t, g_wf2t);

    // weight transposes
    tr_kernel<<<dim3(3*Cc/32, Cc/32),   256>>>(W_attn, pwat,  Cc,   3*Cc);
    tr_kernel<<<dim3(Cc/32,   Cc/32),   256>>>(W_proj, pwpt,  Cc,   Cc);
    tr_kernel<<<dim3(4*Cc/32, Cc/32),   256>>>(W_fc,   pwft,  Cc,   4*Cc);
    tr_kernel<<<dim3(Cc/32,   4*Cc/32), 256>>>(W_fc2,  pwf2t, 4*Cc, Cc);

    // 1. ln1
    ln_kernel<<<BT, 256>>>(x, ln1_w, ln1_b, ph);
    // 2. qkv
    mma_gemm<1><<<dim3(3*Cc/128, BT/128), 256>>>(ph, pwat, b_attn, nullptr,
                                                 nullptr, pq, pk, pvt, BT, 3*Cc, Cc);
    // 3. scores
    scores_mma<<<dim3(Tc/128, Tc/128, Bc*Hc), 256>>>(amask);
    // 4. softmax
    softmax_kernel<<<Bc*Hc*Tc, 256>>>();
    // 5. y = att @ v
    av_mma<<<dim3(Tc/128, Bc*Hc), 256>>>();
    // 6-7. importance
    colsum_kernel<<<Bc*Hc*16, 256>>>();
    impreduce_kernel<<<16, 256>>>();
    // 8. x2 = y@W_proj + b + x
    mma_gemm<2><<<dim3(Cc/128, BT/128), 256>>>(py, pwpt, b_proj, x,
                                               px2, nullptr, nullptr, nullptr, BT, Cc, Cc);
    // 9. ln2
    ln_kernel<<<BT, 256>>>(px2, ln2_w, ln2_b, ph);
    // 10. fc = gelu(h@W_fc + b)
    mma_gemm<3><<<dim3(4*Cc/128, BT/128), 256>>>(ph, pwft, b_fc, nullptr,
                                                 pfc, nullptr, nullptr, nullptr, BT, 4*Cc, Cc);
    // 11. out = fc@W_fc2 + b + x2
    mma_gemm<2><<<dim3(Cc/128, BT/128), 256>>>(pfc, pwf2t, b_fc2, px2,
                                               outp, nullptr, nullptr, nullptr, BT, Cc, 4*Cc);
    // 12. mask + imp
    finalize_kernel<<<1, 1024>>>(amask, thr, outp);
}

// round 5
// speedup vs baseline: 2.3274x; 1.2282x over previous
#include <cuda_runtime.h>
#include <cuda_bf16.h>
#include <cstdint>
#include <math.h>

#define Bc 4
#define Tc 1024
#define Cc 1024
#define Hc 16
#define Dc 64
#define BT (Bc*Tc)          // 4096
#define SINKc 4

// ---------------- scratch ----------------
__device__ float g_h  [(size_t)BT*Cc];
__device__ float g_q  [(size_t)BT*Cc];        // (B,H,T,D)
__device__ float g_k  [(size_t)BT*Cc];        // (B,H,T,D)
__device__ float g_vt [(size_t)BT*Cc];        // (B,H,D,T)
__device__ float g_y  [(size_t)BT*Cc];        // (B,T,C)
__device__ float g_fc [(size_t)BT*4*Cc];
__device__ float g_x2 [(size_t)BT*Cc];
__device__ float g_att[(size_t)Bc*Hc*Tc*Tc];  // 256MB (lower-tri blocks only)
__device__ float g_part[(size_t)Bc*Hc*16*Tc];
__device__ float g_imp[BT];
__device__ float g_wat [(size_t)3*Cc*Cc];
__device__ float g_wpt [(size_t)Cc*Cc];
__device__ float g_wft [(size_t)4*Cc*Cc];
__device__ float g_wf2t[(size_t)Cc*4*Cc];

// ---------------- helpers ----------------
__device__ __forceinline__ uint32_t smem_u32(const void* p) {
    uint32_t r;
    asm("{ .reg .u64 t; cvta.to.shared.u64 t, %1; cvt.u32.u64 %0, t; }"
        : "=r"(r) : "l"(p));
    return r;
}
__device__ __forceinline__ void ldsm4(uint32_t& r0, uint32_t& r1, uint32_t& r2, uint32_t& r3, uint32_t a) {
    asm volatile("ldmatrix.sync.aligned.m8n8.x4.shared.b16 {%0,%1,%2,%3},[%4];"
        : "=r"(r0), "=r"(r1), "=r"(r2), "=r"(r3) : "r"(a));
}
__device__ __forceinline__ void mma_tf32(float* c, uint32_t a0, uint32_t a1, uint32_t a2, uint32_t a3,
                                         uint32_t b0, uint32_t b1) {
    asm volatile("mma.sync.aligned.m16n8k8.row.col.f32.tf32.tf32.f32 "
        "{%0,%1,%2,%3},{%4,%5,%6,%7},{%8,%9},{%0,%1,%2,%3};"
        : "+f"(c[0]), "+f"(c[1]), "+f"(c[2]), "+f"(c[3])
        : "r"(a0), "r"(a1), "r"(a2), "r"(a3), "r"(b0), "r"(b1));
}
__device__ __forceinline__ uint32_t f2tf(float f) {
    uint32_t u;
    asm("cvt.rna.tf32.f32 %0, %1;" : "=r"(u) : "f"(f));
    return u;
}
__device__ __forceinline__ uint4 cvt4(float4 v) {
    uint4 o;
    o.x = f2tf(v.x); o.y = f2tf(v.y); o.z = f2tf(v.z); o.w = f2tf(v.w);
    return o;
}
__device__ __forceinline__ void cp16(uint32_t s, const void* g) {
    asm volatile("cp.async.cg.shared.global [%0], [%1], 16;" :: "r"(s), "l"(g));
}
#define CP_COMMIT() asm volatile("cp.async.commit_group;")
#define CP_WAIT2()  asm volatile("cp.async.wait_group 2;")

// ---------------- weight transpose ----------------
__global__ void __launch_bounds__(256) tr_kernel(const float* __restrict__ W,
                                                 float* __restrict__ Wt, int K, int N) {
    __shared__ float ts[32][33];
    int k0 = blockIdx.y * 32, n0 = blockIdx.x * 32;
    int tx = threadIdx.x & 31, ty = threadIdx.x >> 5;
    #pragma unroll
    for (int i = 0; i < 4; i++) {
        ts[ty + i*8][tx] = W[(size_t)(k0 + ty + i*8) * N + n0 + tx];
    }
    __syncthreads();
    #pragma unroll
    for (int i = 0; i < 4; i++) {
        Wt[(size_t)(n0 + ty + i*8) * K + k0 + tx] = ts[tx][ty + i*8];
    }
}

// ---------------- LayerNorm ----------------
__global__ void __launch_bounds__(256) ln_kernel(const float* __restrict__ x,
                                                 const float* __restrict__ w,
                                                 const float* __restrict__ b,
                                                 float* __restrict__ out) {
    int row = blockIdx.x;
    int tid = threadIdx.x;
    const float* xr = x + (size_t)row * Cc;
    float4 v = *(const float4*)(xr + tid * 4);
    float s  = v.x + v.y + v.z + v.w;
    float s2 = v.x*v.x + v.y*v.y + v.z*v.z + v.w*v.w;
    #pragma unroll
    for (int o = 16; o; o >>= 1) {
        s  += __shfl_xor_sync(~0u, s,  o);
        s2 += __shfl_xor_sync(~0u, s2, o);
    }
    __shared__ float ws[8], ws2[8];
    int wid = tid >> 5, lid = tid & 31;
    if (lid == 0) { ws[wid] = s; ws2[wid] = s2; }
    __syncthreads();
    if (tid < 8) {
        float a = ws[tid], a2 = ws2[tid];
        #pragma unroll
        for (int o = 4; o; o >>= 1) {
            a  += __shfl_xor_sync(0xffu, a,  o);
            a2 += __shfl_xor_sync(0xffu, a2, o);
        }
        if (tid == 0) { ws[0] = a; ws2[0] = a2; }
    }
    __syncthreads();
    float mean = ws[0] * (1.0f / Cc);
    float var  = ws2[0] * (1.0f / Cc) - mean * mean;
    float inv  = rsqrtf(var + 1e-5f);
    int c = tid * 4;
    float4 wv = *(const float4*)(w + c);
    float4 bv = *(const float4*)(b + c);
    float4 ov;
    ov.x = (v.x - mean) * inv * wv.x + bv.x;
    ov.y = (v.y - mean) * inv * wv.y + bv.y;
    ov.z = (v.z - mean) * inv * wv.z + bv.z;
    ov.w = (v.w - mean) * inv * wv.w + bv.w;
    *(float4*)(out + (size_t)row * Cc + c) = ov;
}

// ---------------- tf32 MMA GEMM, cp.async 4-stage, 128x128x16 ----------------
#define GSTAGES 4
#define GSMEM_BYTES (GSTAGES * 2 * 128 * 20 * 4)
template<int EPI>
__global__ void __launch_bounds__(256, 1) mma_gemm(
    const float* __restrict__ A, const float* __restrict__ Bt,
    const float* __restrict__ bias, const float* __restrict__ res,
    float* __restrict__ outF, float* __restrict__ outQ,
    float* __restrict__ outK, float* __restrict__ outVt,
    int M, int N, int K)
{
    extern __shared__ float dsm[];
    typedef float (*Tile)[128][20];
    Tile As = (Tile)dsm;
    Tile Bs = (Tile)(dsm + GSTAGES * 128 * 20);

    int tid = threadIdx.x, lane = tid & 31, wid = tid >> 5;
    int wm = wid & 3, wn = wid >> 2;
    int bm = blockIdx.y * 128, bn = blockIdx.x * 128;

    float acc[2][8][4];
    #pragma unroll
    for (int i = 0; i < 2; i++) {
        #pragma unroll
        for (int j = 0; j < 8; j++) {
            #pragma unroll
            for (int k = 0; k < 4; k++) { acc[i][j][k] = 0.f; }
        }
    }

    int row = tid >> 1, kc = (tid & 1) * 8;
    const float* Ap = A  + (size_t)(bm + row) * K + kc;
    const float* Bp = Bt + (size_t)(bn + row) * K + kc;

    // prologue: stages 0..2
    #pragma unroll
    for (int s = 0; s < GSTAGES - 1; s++) {
        int k0 = s * 16;
        cp16(smem_u32(&As[s][row][kc]),     Ap + k0);
        cp16(smem_u32(&As[s][row][kc + 4]), Ap + k0 + 4);
        cp16(smem_u32(&Bs[s][row][kc]),     Bp + k0);
        cp16(smem_u32(&Bs[s][row][kc + 4]), Bp + k0 + 4);
        CP_COMMIT();
    }

    int nk = K >> 4;
    for (int it = 0; it < nk; it++) {
        CP_WAIT2();
        __syncthreads();
        int st = it & (GSTAGES - 1);
        int nx = it + GSTAGES - 1;
        if (nx < nk) {
            int sx = nx & (GSTAGES - 1);
            int k0 = nx << 4;
            cp16(smem_u32(&As[sx][row][kc]),     Ap + k0);
            cp16(smem_u32(&As[sx][row][kc + 4]), Ap + k0 + 4);
            cp16(smem_u32(&Bs[sx][row][kc]),     Bp + k0);
            cp16(smem_u32(&Bs[sx][row][kc + 4]), Bp + k0 + 4);
        }
        CP_COMMIT();   // commit every iter (may be empty) to keep group counting uniform
        #pragma unroll
        for (int kk = 0; kk < 16; kk += 8) {
            uint32_t af[2][4];
            #pragma unroll
            for (int mt = 0; mt < 2; mt++) {
                ldsm4(af[mt][0], af[mt][1], af[mt][2], af[mt][3],
                      smem_u32(&As[st][wm*32 + mt*16 + (lane & 15)][kk + (lane >> 4) * 4]));
            }
            uint32_t bfr[8][2];
            #pragma unroll
            for (int np = 0; np < 4; np++) {
                uint32_t r0, r1, r2, r3;
                ldsm4(r0, r1, r2, r3,
                      smem_u32(&Bs[st][wn*64 + np*16 + (lane & 15)][kk + (lane >> 4) * 4]));
                bfr[np*2][0] = r0;   bfr[np*2][1] = r2;
                bfr[np*2+1][0] = r1; bfr[np*2+1][1] = r3;
            }
            #pragma unroll
            for (int mt = 0; mt < 2; mt++) {
                #pragma unroll
                for (int nt = 0; nt < 8; nt++) {
                    mma_tf32(acc[mt][nt], af[mt][0], af[mt][1], af[mt][2], af[mt][3],
                             bfr[nt][0], bfr[nt][1]);
                }
            }
        }
        __syncthreads();
    }

    // epilogue
    #pragma unroll
    for (int mt = 0; mt < 2; mt++) {
        #pragma unroll
        for (int nt = 0; nt < 8; nt++) {
            int r0 = bm + wm*32 + mt*16 + (lane >> 2);
            int c0 = bn + wn*64 + nt*8 + (lane & 3) * 2;
            float bb0 = bias[c0], bb1 = bias[c0 + 1];
            #pragma unroll
            for (int rr = 0; rr < 2; rr++) {
                int rg = r0 + rr * 8;
                float v0 = acc[mt][nt][rr*2 + 0] + bb0;
                float v1 = acc[mt][nt][rr*2 + 1] + bb1;
                if (EPI == 1) {
                    int sec = c0 >> 10, wc = c0 & 1023;
                    int h = wc >> 6, d = wc & 63;
                    int bbi = rg >> 10, t = rg & 1023;
                    if (sec == 0) {
                        float2 o; o.x = v0; o.y = v1;
                        *(float2*)&outQ[(((size_t)(bbi*Hc + h))*Tc + t)*Dc + d] = o;
                    } else if (sec == 1) {
                        float2 o; o.x = v0; o.y = v1;
                        *(float2*)&outK[(((size_t)(bbi*Hc + h))*Tc + t)*Dc + d] = o;
                    } else {
                        size_t vb = (((size_t)(bbi*Hc + h))*Dc + d)*Tc + t;
                        outVt[vb] = v0;
                        outVt[vb + Tc] = v1;
                    }
                } else if (EPI == 2) {
                    size_t idx = (size_t)rg * N + c0;
                    float2 rv = *(const float2*)(res + idx);
                    float2 o; o.x = v0 + rv.x; o.y = v1 + rv.y;
                    *(float2*)(outF + idx) = o;
                } else {
                    float g0 = 0.5f * v0 * (1.0f + erff(v0 * 0.70710678118654752f));
                    float g1 = 0.5f * v1 * (1.0f + erff(v1 * 0.70710678118654752f));
                    float2 o; o.x = g0; o.y = g1;
                    *(float2*)&outF[(size_t)rg * N + c0] = o;
                }
            }
        }
    }
}

// ---------------- scores: lower-tri blocks only ----------------
__global__ void __launch_bounds__(256, 1) scores_mma(const int* __restrict__ amask) {
    int bh = blockIdx.z, b = bh >> 4;
    int i0 = blockIdx.y * 128, j0 = blockIdx.x * 128;
    if (j0 > i0) return;              // upper blocks: never written, never read
    size_t base = (size_t)bh * Tc * Tc;
    int tid = threadIdx.x, lane = tid & 31, wid = tid >> 5;

    __shared__ float Qs[128][36];
    __shared__ float Ks[128][36];
    int wm = wid & 3, wn = wid >> 2;
    float acc[2][8][4];
    #pragma unroll
    for (int i = 0; i < 2; i++) {
        #pragma unroll
        for (int j = 0; j < 8; j++) {
            #pragma unroll
            for (int k = 0; k < 4; k++) { acc[i][j][k] = 0.f; }
        }
    }

    int row = tid >> 1, kc = (tid & 1) * 16;
    const float* qp = g_q + ((size_t)bh * Tc + i0 + row) * Dc + kc;
    const float* kp = g_k + ((size_t)bh * Tc + j0 + row) * Dc + kc;

    #pragma unroll
    for (int dc = 0; dc < 64; dc += 32) {
        #pragma unroll
        for (int c4 = 0; c4 < 16; c4 += 4) {
            *(uint4*)&Qs[row][kc + c4] = cvt4(*(const float4*)(qp + dc + c4));
            *(uint4*)&Ks[row][kc + c4] = cvt4(*(const float4*)(kp + dc + c4));
        }
        __syncthreads();
        #pragma unroll
        for (int kk = 0; kk < 32; kk += 8) {
            uint32_t af[2][4];
            #pragma unroll
            for (int mt = 0; mt < 2; mt++) {
                ldsm4(af[mt][0], af[mt][1], af[mt][2], af[mt][3],
                      smem_u32(&Qs[wm*32 + mt*16 + (lane & 15)][kk + (lane >> 4) * 4]));
            }
            uint32_t bfr[8][2];
            #pragma unroll
            for (int np = 0; np < 4; np++) {
                uint32_t r0, r1, r2, r3;
                ldsm4(r0, r1, r2, r3,
                      smem_u32(&Ks[wn*64 + np*16 + (lane & 15)][kk + (lane >> 4) * 4]));
                bfr[np*2][0] = r0;   bfr[np*2][1] = r2;
                bfr[np*2+1][0] = r1; bfr[np*2+1][1] = r3;
            }
            #pragma unroll
            for (int mt = 0; mt < 2; mt++) {
                #pragma unroll
                for (int nt = 0; nt < 8; nt++) {
                    mma_tf32(acc[mt][nt], af[mt][0], af[mt][1], af[mt][2], af[mt][3],
                             bfr[nt][0], bfr[nt][1]);
                }
            }
        }
        __syncthreads();
    }

    #pragma unroll
    for (int mt = 0; mt < 2; mt++) {
        #pragma unroll
        for (int nt = 0; nt < 8; nt++) {
            int r0 = i0 + wm*32 + mt*16 + (lane >> 2);
            int c0 = j0 + wn*64 + nt*8 + (lane & 3) * 2;
            int am0 = amask[b * Tc + c0], am1 = amask[b * Tc + c0 + 1];
            #pragma unroll
            for (int rr = 0; rr < 2; rr++) {
                int rg = r0 + rr * 8;
                float s0 = acc[mt][nt][rr*2 + 0] * 0.125f;
                float s1 = acc[mt][nt][rr*2 + 1] * 0.125f;
                float2 ov;
                ov.x = (c0     <= rg && am0) ? s0 : -1e30f;
                ov.y = (c0 + 1 <= rg && am1) ? s1 : -1e30f;
                *(float2*)&g_att[base + (size_t)rg * Tc + c0] = ov;
            }
        }
    }
}

// ---------------- softmax over valid prefix L = (q/128+1)*128 ----------------
__global__ void __launch_bounds__(256) softmax_kernel() {
    size_t row = blockIdx.x;
    int q = (int)(row & (Tc - 1));
    int L = ((q >> 7) + 1) << 7;
    float* p = g_att + row * Tc;
    int tid = threadIdx.x;
    bool act = (tid * 4) < L;
    float4 v = act ? *(float4*)(p + tid * 4) : make_float4(-1e30f, -1e30f, -1e30f, -1e30f);
    float m = fmaxf(fmaxf(v.x, v.y), fmaxf(v.z, v.w));
    __shared__ float sm[8];
    #pragma unroll
    for (int o = 16; o; o >>= 1) { m = fmaxf(m, __shfl_xor_sync(~0u, m, o)); }
    if ((tid & 31) == 0) sm[tid >> 5] = m;
    __syncthreads();
    if (tid < 8) {
        float t = sm[tid];
        #pragma unroll
        for (int o = 4; o; o >>= 1) { t = fmaxf(t, __shfl_xor_sync(0xffu, t, o)); }
        if (tid == 0) sm[0] = t;
    }
    __syncthreads();
    m = sm[0];
    float4 ev;
    ev.x = __expf(v.x - m); ev.y = __expf(v.y - m);
    ev.z = __expf(v.z - m); ev.w = __expf(v.w - m);
    float s = ev.x + ev.y + ev.z + ev.w;
    __shared__ float ssum[8];
    #pragma unroll
    for (int o = 16; o; o >>= 1) { s += __shfl_xor_sync(~0u, s, o); }
    if ((tid & 31) == 0) ssum[tid >> 5] = s;
    __syncthreads();
    if (tid < 8) {
        float t = ssum[tid];
        #pragma unroll
        for (int o = 4; o; o >>= 1) { t += __shfl_xor_sync(0xffu, t, o); }
        if (tid == 0) ssum[0] = t;
    }
    __syncthreads();
    float invs = 1.0f / ssum[0];
    if (act) {
        ev.x *= invs; ev.y *= invs; ev.z *= invs; ev.w *= invs;
        *(float4*)(p + tid * 4) = ev;
    }
}

// ---------------- y = att @ v ----------------
__global__ void __launch_bounds__(256, 1) av_mma() {
    int bh = blockIdx.y, b = bh >> 4, h = bh & 15;
    int i0 = blockIdx.x * 128;
    __shared__ float Ps[128][36];
    __shared__ float Vs[64][36];
    int tid = threadIdx.x, lane = tid & 31, wid = tid >> 5;

    float acc[8][4];
    #pragma unroll
    for (int j = 0; j < 8; j++) {
        #pragma unroll
        for (int k = 0; k < 4; k++) { acc[j][k] = 0.f; }
    }

    const float* attp = g_att + ((size_t)bh * Tc + i0) * Tc;
    const float* vtp  = g_vt + (size_t)bh * Dc * Tc;
    int rowp = tid >> 1, kcp = (tid & 1) * 16;
    int rowv = tid >> 2, kcv = (tid & 3) * 8;
    int kmax = i0 + 128;

    for (int k0 = 0; k0 < kmax; k0 += 32) {
        const float* psrc = attp + (size_t)rowp * Tc + k0 + kcp;
        #pragma unroll
        for (int c4 = 0; c4 < 16; c4 += 4) {
            *(uint4*)&Ps[rowp][kcp + c4] = cvt4(*(const float4*)(psrc + c4));
        }
        const float* vsrc = vtp + (size_t)rowv * Tc + k0 + kcv;
        *(uint4*)&Vs[rowv][kcv]     = cvt4(*(const float4*)vsrc);
        *(uint4*)&Vs[rowv][kcv + 4] = cvt4(*(const float4*)(vsrc + 4));
        __syncthreads();
        #pragma unroll
        for (int kk = 0; kk < 32; kk += 8) {
            uint32_t af[4];
            ldsm4(af[0], af[1], af[2], af[3],
                  smem_u32(&Ps[wid*16 + (lane & 15)][kk + (lane >> 4) * 4]));
            uint32_t bfr[8][2];
            #pragma unroll
            for (int np = 0; np < 4; np++) {
                uint32_t r0, r1, r2, r3;
                ldsm4(r0, r1, r2, r3,
                      smem_u32(&Vs[np*16 + (lane & 15)][kk + (lane >> 4) * 4]));
                bfr[np*2][0] = r0;   bfr[np*2][1] = r2;
                bfr[np*2+1][0] = r1; bfr[np*2+1][1] = r3;
            }
            #pragma unroll
            for (int nt = 0; nt < 8; nt++) {
                mma_tf32(acc[nt], af[0], af[1], af[2], af[3], bfr[nt][0], bfr[nt][1]);
            }
        }
        __syncthreads();
    }

    #pragma unroll
    for (int nt = 0; nt < 8; nt++) {
        int q0 = i0 + wid*16 + (lane >> 2);
        int d0 = nt*8 + (lane & 3) * 2;
        #pragma unroll
        for (int rr = 0; rr < 2; rr++) {
            int q = q0 + rr * 8;
            float2 o; o.x = acc[nt][rr*2]; o.y = acc[nt][rr*2 + 1];
            *(float2*)&g_y[(size_t)(b*Tc + q) * Cc + h*64 + d0] = o;
        }
    }
}

// ---------------- colsum partials (triangle-aware) ----------------
__global__ void __launch_bounds__(256) colsum_kernel() {
    int idx = blockIdx.x;
    int bh = idx >> 4, qc = idx & 15;
    int tid = threadIdx.x;
    int kend = (((qc >> 1) + 1) << 7);   // cols with written data in this row-chunk
    float4 acc = make_float4(0.f, 0.f, 0.f, 0.f);
    if (tid * 4 < kend) {
        const float* base = g_att + ((size_t)bh * Tc + qc * 64) * Tc;
        for (int q = 0; q < 64; q++) {
            float4 v = *(const float4*)(base + (size_t)q * Tc + tid * 4);
            acc.x += v.x; acc.y += v.y; acc.z += v.z; acc.w += v.w;
        }
    }
    *(float4*)&g_part[(size_t)idx * Tc + tid * 4] = acc;
}

__global__ void __launch_bounds__(256) impreduce_kernel() {
    int gt = blockIdx.x * 256 + threadIdx.x;
    int b = gt >> 10, t = gt & 1023;
    float s = 0.f;
    const float* p = g_part + (size_t)b * 256 * Tc + t;
    for (int i = 0; i < 256; i++) { s += p[(size_t)i * Tc]; }
    float posn = (float)(Tc - t) / (float)Tc;
    g_imp[gt] = (s / (float)Hc) / (posn + 1e-8f);
}

__global__ void __launch_bounds__(1024) finalize_kernel(const int* __restrict__ amask,
                                                        const float* __restrict__ thrp,
                                                        float* __restrict__ outp) {
    int tid = threadIdx.x;
    float m = -3.4e38f;
    for (int i = tid; i < BT; i += 1024) { m = fmaxf(m, g_imp[i]); }
    __shared__ float red[32];
    #pragma unroll
    for (int o = 16; o; o >>= 1) { m = fmaxf(m, __shfl_xor_sync(~0u, m, o)); }
    if ((tid & 31) == 0) red[tid >> 5] = m;
    __syncthreads();
    if (tid < 32) {
        float v = red[tid];
        #pragma unroll
        for (int o = 16; o; o >>= 1) { v = fmaxf(v, __shfl_xor_sync(~0u, v, o)); }
        if (tid == 0) red[0] = v;
    }
    __syncthreads();
    float maxv = red[0];
    float thr = *thrp;
    float* maskp = outp + (size_t)BT * Cc;
    float* impp  = maskp + BT;
    for (int i = tid; i < BT; i += 1024) {
        int t = i & 1023;
        float iv = g_imp[i];
        if (t < SINKc) iv = maxv + 1.0f;
        float mk = (iv >= thr) ? 1.0f : 0.0f;
        if (t < SINKc) mk = 1.0f;
        if (amask[i] == 0) mk = 0.0f;
        maskp[i] = mk;
        impp[i]  = iv;
    }
}

// ---------------- launch ----------------
extern "C" void kernel_launch(void* const* d_in, const int* in_sizes, int n_in,
                              void* d_out, int out_size) {
    (void)in_sizes; (void)n_in; (void)out_size;
    const float* x      = (const float*)d_in[0];
    const int*   amask  = (const int*)  d_in[1];
    const float* W_attn = (const float*)d_in[2];
    const float* b_attn = (const float*)d_in[3];
    const float* W_proj = (const float*)d_in[4];
    const float* b_proj = (const float*)d_in[5];
    const float* ln1_w  = (const float*)d_in[6];
    const float* ln1_b  = (const float*)d_in[7];
    const float* ln2_w  = (const float*)d_in[8];
    const float* ln2_b  = (const float*)d_in[9];
    const float* W_fc   = (const float*)d_in[10];
    const float* b_fc   = (const float*)d_in[11];
    const float* W_fc2  = (const float*)d_in[12];
    const float* b_fc2  = (const float*)d_in[13];
    const float* thr    = (const float*)d_in[14];
    float* outp = (float*)d_out;

    float *ph, *pq, *pk, *pvt, *py, *pfc, *px2, *pwat, *pwpt, *pwft, *pwf2t;
    cudaGetSymbolAddress((void**)&ph,    g_h);
    cudaGetSymbolAddress((void**)&pq,    g_q);
    cudaGetSymbolAddress((void**)&pk,    g_k);
    cudaGetSymbolAddress((void**)&pvt,   g_vt);
    cudaGetSymbolAddress((void**)&py,    g_y);
    cudaGetSymbolAddress((void**)&pfc,   g_fc);
    cudaGetSymbolAddress((void**)&px2,   g_x2);
    cudaGetSymbolAddress((void**)&pwat,  g_wat);
    cudaGetSymbolAddress((void**)&pwpt,  g_wpt);
    cudaGetSymbolAddress((void**)&pwft,  g_wft);
    cudaGetSymbolAddress((void**)&pwf2t, g_wf2t);

    // raise dynamic smem limit (idempotent host call, non-stream; capture-safe)
    cudaFuncSetAttribute(mma_gemm<1>, cudaFuncAttributeMaxDynamicSharedMemorySize, GSMEM_BYTES);
    cudaFuncSetAttribute(mma_gemm<2>, cudaFuncAttributeMaxDynamicSharedMemorySize, GSMEM_BYTES);
    cudaFuncSetAttribute(mma_gemm<3>, cudaFuncAttributeMaxDynamicSharedMemorySize, GSMEM_BYTES);

    tr_kernel<<<dim3(3*Cc/32, Cc/32),   256>>>(W_attn, pwat,  Cc,   3*Cc);
    tr_kernel<<<dim3(Cc/32,   Cc/32),   256>>>(W_proj, pwpt,  Cc,   Cc);
    tr_kernel<<<dim3(4*Cc/32, Cc/32),   256>>>(W_fc,   pwft,  Cc,   4*Cc);
    tr_kernel<<<dim3(Cc/32,   4*Cc/32), 256>>>(W_fc2,  pwf2t, 4*Cc, Cc);

    ln_kernel<<<BT, 256>>>(x, ln1_w, ln1_b, ph);
    mma_gemm<1><<<dim3(3*Cc/128, BT/128), 256, GSMEM_BYTES>>>(ph, pwat, b_attn, nullptr,
                                                 nullptr, pq, pk, pvt, BT, 3*Cc, Cc);
    scores_mma<<<dim3(Tc/128, Tc/128, Bc*Hc), 256>>>(amask);
    softmax_kernel<<<Bc*Hc*Tc, 256>>>();
    av_mma<<<dim3(Tc/128, Bc*Hc), 256>>>();
    colsum_kernel<<<Bc*Hc*16, 256>>>();
    impreduce_kernel<<<16, 256>>>();
    mma_gemm<2><<<dim3(Cc/128, BT/128), 256, GSMEM_BYTES>>>(py, pwpt, b_proj, x,
                                               px2, nullptr, nullptr, nullptr, BT, Cc, Cc);
    ln_kernel<<<BT, 256>>>(px2, ln2_w, ln2_b, ph);
    mma_gemm<3><<<dim3(4*Cc/128, BT/128), 256, GSMEM_BYTES>>>(ph, pwft, b_fc, nullptr,
                                                 pfc, nullptr, nullptr, nullptr, BT, 4*Cc, Cc);
    mma_gemm<2><<<dim3(Cc/128, BT/128), 256, GSMEM_BYTES>>>(pfc, pwf2t, b_fc2, px2,
                                               outp, nullptr, nullptr, nullptr, BT, Cc, 4*Cc);
    finalize_kernel<<<1, 1024>>>(amask, thr, outp);
}

// round 6
// speedup vs baseline: 2.3518x; 1.0105x over previous
#include <cuda_runtime.h>
#include <cuda_bf16.h>
#include <cstdint>
#include <math.h>

#define Bc 4
#define Tc 1024
#define Cc 1024
#define Hc 16
#define Dc 64
#define BT (Bc*Tc)
#define SINKc 4

// ---------------- scratch ----------------
__device__ float g_h  [(size_t)BT*Cc];
__device__ float g_q  [(size_t)BT*Cc];        // (B,H,T,D) tf32-rounded
__device__ float g_k  [(size_t)BT*Cc];
__device__ float g_vt [(size_t)BT*Cc];        // (B,H,D,T)
__device__ float g_y  [(size_t)BT*Cc];        // (B,T,C)
__device__ float g_fc [(size_t)BT*4*Cc];
__device__ float g_x2 [(size_t)BT*Cc];
__device__ float g_part[(size_t)Bc*Hc*8*Tc]; // colsums per (bh,qblk)
__device__ float g_imp[BT];
__device__ float g_wat [(size_t)3*Cc*Cc];
__device__ float g_wpt [(size_t)Cc*Cc];
__device__ float g_wft [(size_t)4*Cc*Cc];
__device__ float g_wf2t[(size_t)Cc*4*Cc];

// ---------------- helpers ----------------
__device__ __forceinline__ uint32_t smem_u32(const void* p) {
    uint32_t r;
    asm("{ .reg .u64 t; cvta.to.shared.u64 t, %1; cvt.u32.u64 %0, t; }"
        : "=r"(r) : "l"(p));
    return r;
}
__device__ __forceinline__ void ldsm4(uint32_t& r0, uint32_t& r1, uint32_t& r2, uint32_t& r3, uint32_t a) {
    asm volatile("ldmatrix.sync.aligned.m8n8.x4.shared.b16 {%0,%1,%2,%3},[%4];"
        : "=r"(r0), "=r"(r1), "=r"(r2), "=r"(r3) : "r"(a));
}
__device__ __forceinline__ void mma_tf32(float* c, uint32_t a0, uint32_t a1, uint32_t a2, uint32_t a3,
                                         uint32_t b0, uint32_t b1) {
    asm volatile("mma.sync.aligned.m16n8k8.row.col.f32.tf32.tf32.f32 "
        "{%0,%1,%2,%3},{%4,%5,%6,%7},{%8,%9},{%0,%1,%2,%3};"
        : "+f"(c[0]), "+f"(c[1]), "+f"(c[2]), "+f"(c[3])
        : "r"(a0), "r"(a1), "r"(a2), "r"(a3), "r"(b0), "r"(b1));
}
__device__ __forceinline__ uint32_t f2tf(float f) {
    uint32_t u;
    asm("cvt.rna.tf32.f32 %0, %1;" : "=r"(u) : "f"(f));
    return u;
}
__device__ __forceinline__ float rnd(float f) { return __uint_as_float(f2tf(f)); }
__device__ __forceinline__ uint4 cvt4(float4 v) {
    uint4 o;
    o.x = f2tf(v.x); o.y = f2tf(v.y); o.z = f2tf(v.z); o.w = f2tf(v.w);
    return o;
}
__device__ __forceinline__ void cp16(uint32_t s, const void* g) {
    asm volatile("cp.async.cg.shared.global [%0], [%1], 16;" :: "r"(s), "l"(g));
}
#define CP_COMMIT() asm volatile("cp.async.commit_group;")
#define CP_WAIT2()  asm volatile("cp.async.wait_group 2;")

// ---------------- weight transpose (tf32-rounded) ----------------
__global__ void __launch_bounds__(256) tr_kernel(const float* __restrict__ W,
                                                 float* __restrict__ Wt, int K, int N) {
    __shared__ float ts[32][33];
    int k0 = blockIdx.y * 32, n0 = blockIdx.x * 32;
    int tx = threadIdx.x & 31, ty = threadIdx.x >> 5;
    #pragma unroll
    for (int i = 0; i < 4; i++) {
        ts[ty + i*8][tx] = W[(size_t)(k0 + ty + i*8) * N + n0 + tx];
    }
    __syncthreads();
    #pragma unroll
    for (int i = 0; i < 4; i++) {
        Wt[(size_t)(n0 + ty + i*8) * K + k0 + tx] = rnd(ts[tx][ty + i*8]);
    }
}

// ---------------- LayerNorm (tf32-rounded out) ----------------
__global__ void __launch_bounds__(256) ln_kernel(const float* __restrict__ x,
                                                 const float* __restrict__ w,
                                                 const float* __restrict__ b,
                                                 float* __restrict__ out) {
    int row = blockIdx.x;
    int tid = threadIdx.x;
    const float* xr = x + (size_t)row * Cc;
    float4 v = *(const float4*)(xr + tid * 4);
    float s  = v.x + v.y + v.z + v.w;
    float s2 = v.x*v.x + v.y*v.y + v.z*v.z + v.w*v.w;
    #pragma unroll
    for (int o = 16; o; o >>= 1) {
        s  += __shfl_xor_sync(~0u, s,  o);
        s2 += __shfl_xor_sync(~0u, s2, o);
    }
    __shared__ float ws[8], ws2[8];
    int wid = tid >> 5, lid = tid & 31;
    if (lid == 0) { ws[wid] = s; ws2[wid] = s2; }
    __syncthreads();
    if (tid < 8) {
        float a = ws[tid], a2 = ws2[tid];
        #pragma unroll
        for (int o = 4; o; o >>= 1) {
            a  += __shfl_xor_sync(0xffu, a,  o);
            a2 += __shfl_xor_sync(0xffu, a2, o);
        }
        if (tid == 0) { ws[0] = a; ws2[0] = a2; }
    }
    __syncthreads();
    float mean = ws[0] * (1.0f / Cc);
    float var  = ws2[0] * (1.0f / Cc) - mean * mean;
    float inv  = rsqrtf(var + 1e-5f);
    int c = tid * 4;
    float4 wv = *(const float4*)(w + c);
    float4 bv = *(const float4*)(b + c);
    float4 ov;
    ov.x = rnd((v.x - mean) * inv * wv.x + bv.x);
    ov.y = rnd((v.y - mean) * inv * wv.y + bv.y);
    ov.z = rnd((v.z - mean) * inv * wv.z + bv.z);
    ov.w = rnd((v.w - mean) * inv * wv.w + bv.w);
    *(float4*)(out + (size_t)row * Cc + c) = ov;
}

// ---------------- tf32 MMA GEMM, cp.async 4-stage ----------------
#define GSTAGES 4
#define GSMEM_BYTES (GSTAGES * 2 * 128 * 20 * 4)
template<int EPI>
__global__ void __launch_bounds__(256, 1) mma_gemm(
    const float* __restrict__ A, const float* __restrict__ Bt,
    const float* __restrict__ bias, const float* __restrict__ res,
    float* __restrict__ outF, float* __restrict__ outQ,
    float* __restrict__ outK, float* __restrict__ outVt,
    int M, int N, int K)
{
    extern __shared__ float dsm[];
    typedef float (*Tile)[128][20];
    Tile As = (Tile)dsm;
    Tile Bs = (Tile)(dsm + GSTAGES * 128 * 20);

    int tid = threadIdx.x, lane = tid & 31, wid = tid >> 5;
    int wm = wid & 3, wn = wid >> 2;
    int bm = blockIdx.y * 128, bn = blockIdx.x * 128;

    float acc[2][8][4];
    #pragma unroll
    for (int i = 0; i < 2; i++) {
        #pragma unroll
        for (int j = 0; j < 8; j++) {
            #pragma unroll
            for (int k = 0; k < 4; k++) { acc[i][j][k] = 0.f; }
        }
    }

    int row = tid >> 1, kc = (tid & 1) * 8;
    const float* Ap = A  + (size_t)(bm + row) * K + kc;
    const float* Bp = Bt + (size_t)(bn + row) * K + kc;

    #pragma unroll
    for (int s = 0; s < GSTAGES - 1; s++) {
        int k0 = s * 16;
        cp16(smem_u32(&As[s][row][kc]),     Ap + k0);
        cp16(smem_u32(&As[s][row][kc + 4]), Ap + k0 + 4);
        cp16(smem_u32(&Bs[s][row][kc]),     Bp + k0);
        cp16(smem_u32(&Bs[s][row][kc + 4]), Bp + k0 + 4);
        CP_COMMIT();
    }

    int nk = K >> 4;
    for (int it = 0; it < nk; it++) {
        CP_WAIT2();
        __syncthreads();
        int st = it & (GSTAGES - 1);
        int nx = it + GSTAGES - 1;
        if (nx < nk) {
            int sx = nx & (GSTAGES - 1);
            int k0 = nx << 4;
            cp16(smem_u32(&As[sx][row][kc]),     Ap + k0);
            cp16(smem_u32(&As[sx][row][kc + 4]), Ap + k0 + 4);
            cp16(smem_u32(&Bs[sx][row][kc]),     Bp + k0);
            cp16(smem_u32(&Bs[sx][row][kc + 4]), Bp + k0 + 4);
        }
        CP_COMMIT();
        #pragma unroll
        for (int kk = 0; kk < 16; kk += 8) {
            uint32_t af[2][4];
            #pragma unroll
            for (int mt = 0; mt < 2; mt++) {
                ldsm4(af[mt][0], af[mt][1], af[mt][2], af[mt][3],
                      smem_u32(&As[st][wm*32 + mt*16 + (lane & 15)][kk + (lane >> 4) * 4]));
            }
            uint32_t bfr[8][2];
            #pragma unroll
            for (int np = 0; np < 4; np++) {
                uint32_t r0, r1, r2, r3;
                ldsm4(r0, r1, r2, r3,
                      smem_u32(&Bs[st][wn*64 + np*16 + (lane & 15)][kk + (lane >> 4) * 4]));
                bfr[np*2][0] = r0;   bfr[np*2][1] = r2;
                bfr[np*2+1][0] = r1; bfr[np*2+1][1] = r3;
            }
            #pragma unroll
            for (int mt = 0; mt < 2; mt++) {
                #pragma unroll
                for (int nt = 0; nt < 8; nt++) {
                    mma_tf32(acc[mt][nt], af[mt][0], af[mt][1], af[mt][2], af[mt][3],
                             bfr[nt][0], bfr[nt][1]);
                }
            }
        }
    }

    #pragma unroll
    for (int mt = 0; mt < 2; mt++) {
        #pragma unroll
        for (int nt = 0; nt < 8; nt++) {
            int r0 = bm + wm*32 + mt*16 + (lane >> 2);
            int c0 = bn + wn*64 + nt*8 + (lane & 3) * 2;
            float bb0 = bias[c0], bb1 = bias[c0 + 1];
            #pragma unroll
            for (int rr = 0; rr < 2; rr++) {
                int rg = r0 + rr * 8;
                float v0 = acc[mt][nt][rr*2 + 0] + bb0;
                float v1 = acc[mt][nt][rr*2 + 1] + bb1;
                if (EPI == 1) {
                    int sec = c0 >> 10, wc = c0 & 1023;
                    int h = wc >> 6, d = wc & 63;
                    int bbi = rg >> 10, t = rg & 1023;
                    if (sec == 0) {
                        float2 o; o.x = rnd(v0); o.y = rnd(v1);
                        *(float2*)&outQ[(((size_t)(bbi*Hc + h))*Tc + t)*Dc + d] = o;
                    } else if (sec == 1) {
                        float2 o; o.x = rnd(v0); o.y = rnd(v1);
                        *(float2*)&outK[(((size_t)(bbi*Hc + h))*Tc + t)*Dc + d] = o;
                    } else {
                        size_t vb = (((size_t)(bbi*Hc + h))*Dc + d)*Tc + t;
                        outVt[vb] = rnd(v0);
                        outVt[vb + Tc] = rnd(v1);
                    }
                } else if (EPI == 2) {
                    size_t idx = (size_t)rg * N + c0;
                    float2 rv = *(const float2*)(res + idx);
                    float2 o; o.x = v0 + rv.x; o.y = v1 + rv.y;
                    *(float2*)(outF + idx) = o;
                } else {
                    float g0 = 0.5f * v0 * (1.0f + erff(v0 * 0.70710678118654752f));
                    float g1 = 0.5f * v1 * (1.0f + erff(v1 * 0.70710678118654752f));
                    float2 o; o.x = rnd(g0); o.y = rnd(g1);
                    *(float2*)&outF[(size_t)rg * N + c0] = o;
                }
            }
        }
    }
}

// ================ fused flash attention (two-pass) ================
// smem layout (floats): Qs[128][68] | Ks[128][68] | Ss[128][132] | Vs[64][132]
//                       | m_s[128] | l_s[128] | mn_s[128] | red[256]
#define OFF_QS 0
#define OFF_KS 8704
#define OFF_SS 17408
#define OFF_VS 34304
#define OFF_M  42752
#define OFF_L  42880
#define OFF_MN 43008
#define OFF_RED 43136
#define ATT_SMEM_FLOATS 43392
#define ATT_SMEM_BYTES (ATT_SMEM_FLOATS * 4)

__device__ __forceinline__ void compute_S(
    const float (*Qs)[68], const float (*Ks)[68],
    int wm, int wn, int lane, float acc[2][8][4])
{
    #pragma unroll
    for (int i = 0; i < 2; i++) {
        #pragma unroll
        for (int j = 0; j < 8; j++) {
            #pragma unroll
            for (int k = 0; k < 4; k++) { acc[i][j][k] = 0.f; }
        }
    }
    #pragma unroll
    for (int kk = 0; kk < 64; kk += 8) {
        uint32_t af[2][4];
        #pragma unroll
        for (int mt = 0; mt < 2; mt++) {
            ldsm4(af[mt][0], af[mt][1], af[mt][2], af[mt][3],
                  smem_u32(&Qs[wm*32 + mt*16 + (lane & 15)][kk + (lane >> 4) * 4]));
        }
        uint32_t bfr[8][2];
        #pragma unroll
        for (int np = 0; np < 4; np++) {
            uint32_t r0, r1, r2, r3;
            ldsm4(r0, r1, r2, r3,
                  smem_u32(&Ks[wn*64 + np*16 + (lane & 15)][kk + (lane >> 4) * 4]));
            bfr[np*2][0] = r0;   bfr[np*2][1] = r2;
            bfr[np*2+1][0] = r1; bfr[np*2+1][1] = r3;
        }
        #pragma unroll
        for (int mt = 0; mt < 2; mt++) {
            #pragma unroll
            for (int nt = 0; nt < 8; nt++) {
                mma_tf32(acc[mt][nt], af[mt][0], af[mt][1], af[mt][2], af[mt][3],
                         bfr[nt][0], bfr[nt][1]);
            }
        }
    }
}

__global__ void __launch_bounds__(256, 1) flash_kernel(const int* __restrict__ amask) {
    extern __shared__ float sm[];
    float (*Qs)[68]  = (float(*)[68]) (sm + OFF_QS);
    float (*Ks)[68]  = (float(*)[68]) (sm + OFF_KS);
    float (*Ss)[132] = (float(*)[132])(sm + OFF_SS);
    float (*Vs)[132] = (float(*)[132])(sm + OFF_VS);
    float* m_s  = sm + OFF_M;
    float* l_s  = sm + OFF_L;
    float* mn_s = sm + OFF_MN;
    float* red  = sm + OFF_RED;

    int bh = blockIdx.y, b = bh >> 4, h = bh & 15;
    int qblk = (int)(gridDim.x - 1 - blockIdx.x);   // heavy blocks first
    int i0 = qblk << 7;
    int tid = threadIdx.x, lane = tid & 31, wid = tid >> 5;
    int wm = wid & 3, wn = wid >> 2;

    // load Q block (persistent, tf32 re-round is identity: already rounded)
    {
        int row = tid >> 1, c0 = (tid & 1) * 32;
        const float* qp = g_q + ((size_t)bh*Tc + i0 + row)*Dc + c0;
        #pragma unroll
        for (int c4 = 0; c4 < 32; c4 += 4) {
            *(float4*)&Qs[row][c0 + c4] = *(const float4*)(qp + c4);
        }
    }
    if (tid < 128) { m_s[tid] = -3.0e38f; l_s[tid] = 0.f; }
    __syncthreads();

    int nj = qblk + 1;
    float acc[2][8][4];

    // ---------- pass A: row max + sum ----------
    for (int jb = 0; jb < nj; jb++) {
        int j0 = jb << 7;
        {
            int row = tid >> 1, c0 = (tid & 1) * 32;
            const float* kp = g_k + ((size_t)bh*Tc + j0 + row)*Dc + c0;
            #pragma unroll
            for (int c4 = 0; c4 < 32; c4 += 4) {
                *(float4*)&Ks[row][c0 + c4] = *(const float4*)(kp + c4);
            }
        }
        __syncthreads();
        compute_S(Qs, Ks, wm, wn, lane, acc);
        // scale + mask in place
        #pragma unroll
        for (int mt = 0; mt < 2; mt++) {
            #pragma unroll
            for (int nt = 0; nt < 8; nt++) {
                int c0 = j0 + wn*64 + nt*8 + (lane & 3) * 2;
                int am0 = amask[b*Tc + c0], am1 = amask[b*Tc + c0 + 1];
                #pragma unroll
                for (int rr = 0; rr < 2; rr++) {
                    int r = i0 + wm*32 + mt*16 + rr*8 + (lane >> 2);
                    float s0 = acc[mt][nt][rr*2 + 0] * 0.125f;
                    float s1 = acc[mt][nt][rr*2 + 1] * 0.125f;
                    acc[mt][nt][rr*2 + 0] = (c0     <= r && am0) ? s0 : -1e30f;
                    acc[mt][nt][rr*2 + 1] = (c0 + 1 <= r && am1) ? s1 : -1e30f;
                }
            }
        }
        // block row-max
        #pragma unroll
        for (int mt = 0; mt < 2; mt++) {
            #pragma unroll
            for (int rr = 0; rr < 2; rr++) {
                float bm = -3.4e38f;
                #pragma unroll
                for (int nt = 0; nt < 8; nt++) {
                    bm = fmaxf(bm, fmaxf(acc[mt][nt][rr*2], acc[mt][nt][rr*2 + 1]));
                }
                bm = fmaxf(bm, __shfl_xor_sync(~0u, bm, 1));
                bm = fmaxf(bm, __shfl_xor_sync(~0u, bm, 2));
                if ((lane & 3) == 0) {
                    red[wn*128 + wm*32 + mt*16 + rr*8 + (lane >> 2)] = bm;
                }
            }
        }
        __syncthreads();
        if (wn == 0 && (lane & 3) == 0) {
            #pragma unroll
            for (int mt = 0; mt < 2; mt++) {
                #pragma unroll
                for (int rr = 0; rr < 2; rr++) {
                    int rl = wm*32 + mt*16 + rr*8 + (lane >> 2);
                    mn_s[rl] = fmaxf(m_s[rl], fmaxf(red[rl], red[128 + rl]));
                }
            }
        }
        __syncthreads();
        // block row-sum of exp
        #pragma unroll
        for (int mt = 0; mt < 2; mt++) {
            #pragma unroll
            for (int rr = 0; rr < 2; rr++) {
                int rl = wm*32 + mt*16 + rr*8 + (lane >> 2);
                float mnew = mn_s[rl];
                float e = 0.f;
                #pragma unroll
                for (int nt = 0; nt < 8; nt++) {
                    e += __expf(acc[mt][nt][rr*2]     - mnew);
                    e += __expf(acc[mt][nt][rr*2 + 1] - mnew);
                }
                e += __shfl_xor_sync(~0u, e, 1);
                e += __shfl_xor_sync(~0u, e, 2);
                if ((lane & 3) == 0) { red[wn*128 + rl] = e; }
            }
        }
        __syncthreads();
        if (wn == 0 && (lane & 3) == 0) {
            #pragma unroll
            for (int mt = 0; mt < 2; mt++) {
                #pragma unroll
                for (int rr = 0; rr < 2; rr++) {
                    int rl = wm*32 + mt*16 + rr*8 + (lane >> 2);
                    float mnew = mn_s[rl];
                    l_s[rl] = l_s[rl] * __expf(m_s[rl] - mnew) + red[rl] + red[128 + rl];
                    m_s[rl] = mnew;
                }
            }
        }
        __syncthreads();
    }
    // invert l
    if (tid < 128) {
        float l = l_s[tid];
        l_s[tid] = (l > 0.f) ? (1.0f / l) : 0.f;
    }
    __syncthreads();

    float acco[8][4];
    #pragma unroll
    for (int j = 0; j < 8; j++) {
        #pragma unroll
        for (int k = 0; k < 4; k++) { acco[j][k] = 0.f; }
    }

    // ---------- pass B: P, colsum, O = P@V ----------
    for (int jb = 0; jb < nj; jb++) {
        int j0 = jb << 7;
        {
            int row = tid >> 1, c0 = (tid & 1) * 32;
            const float* kp = g_k + ((size_t)bh*Tc + j0 + row)*Dc + c0;
            #pragma unroll
            for (int c4 = 0; c4 < 32; c4 += 4) {
                *(float4*)&Ks[row][c0 + c4] = *(const float4*)(kp + c4);
            }
            int rowv = tid >> 2, cv0 = (tid & 3) * 32;
            const float* vp = g_vt + ((size_t)bh*Dc + rowv)*Tc + j0 + cv0;
            #pragma unroll
            for (int c4 = 0; c4 < 32; c4 += 4) {
                *(float4*)&Vs[rowv][cv0 + c4] = *(const float4*)(vp + c4);
            }
        }
        __syncthreads();
        compute_S(Qs, Ks, wm, wn, lane, acc);
        // P = exp(s - m) * invl -> Ss (tf32-rounded)
        #pragma unroll
        for (int mt = 0; mt < 2; mt++) {
            #pragma unroll
            for (int nt = 0; nt < 8; nt++) {
                int cl = wn*64 + nt*8 + (lane & 3) * 2;
                int c0 = j0 + cl;
                int am0 = amask[b*Tc + c0], am1 = amask[b*Tc + c0 + 1];
                #pragma unroll
                for (int rr = 0; rr < 2; rr++) {
                    int rl = wm*32 + mt*16 + rr*8 + (lane >> 2);
                    int r = i0 + rl;
                    float ml = m_s[rl], il = l_s[rl];
                    float s0 = acc[mt][nt][rr*2 + 0] * 0.125f;
                    float s1 = acc[mt][nt][rr*2 + 1] * 0.125f;
                    float p0 = (c0     <= r && am0) ? (__expf(s0 - ml) * il) : 0.f;
                    float p1 = (c0 + 1 <= r && am1) ? (__expf(s1 - ml) * il) : 0.f;
                    float2 pv; pv.x = rnd(p0); pv.y = rnd(p1);
                    *(float2*)&Ss[rl][cl] = pv;
                }
            }
        }
        __syncthreads();
        // exact colsum of P for this j-block (deterministic)
        if (tid < 128) {
            float s = 0.f;
            #pragma unroll 8
            for (int r = 0; r < 128; r++) { s += Ss[r][tid]; }
            g_part[((size_t)bh*8 + qblk)*Tc + j0 + tid] = s;
        }
        // O += P @ V
        #pragma unroll
        for (int kk = 0; kk < 128; kk += 8) {
            uint32_t af[4];
            ldsm4(af[0], af[1], af[2], af[3],
                  smem_u32(&Ss[wid*16 + (lane & 15)][kk + (lane >> 4) * 4]));
            uint32_t bfr[8][2];
            #pragma unroll
            for (int np = 0; np < 4; np++) {
                uint32_t r0, r1, r2, r3;
                ldsm4(r0, r1, r2, r3,
                      smem_u32(&Vs[np*16 + (lane & 15)][kk + (lane >> 4) * 4]));
                bfr[np*2][0] = r0;   bfr[np*2][1] = r2;
                bfr[np*2+1][0] = r1; bfr[np*2+1][1] = r3;
            }
            #pragma unroll
            for (int nt = 0; nt < 8; nt++) {
                mma_tf32(acco[nt], af[0], af[1], af[2], af[3], bfr[nt][0], bfr[nt][1]);
            }
        }
        __syncthreads();
    }

    // write y (tf32-rounded; feeds proj GEMM only)
    #pragma unroll
    for (int nt = 0; nt < 8; nt++) {
        int q0 = i0 + wid*16 + (lane >> 2);
        int d0 = nt*8 + (lane & 3) * 2;
        #pragma unroll
        for (int rr = 0; rr < 2; rr++) {
            int q = q0 + rr * 8;
            float2 o; o.x = rnd(acco[nt][rr*2]); o.y = rnd(acco[nt][rr*2 + 1]);
            *(float2*)&g_y[(size_t)(b*Tc + q) * Cc + h*64 + d0] = o;
        }
    }
    // zero untouched colsum tail
    for (int c = i0 + 128 + tid; c < Tc; c += 256) {
        g_part[((size_t)bh*8 + qblk)*Tc + c] = 0.f;
    }
}

// ---------------- imp reduce: sum over 16 heads x 8 qblks ----------------
__global__ void __launch_bounds__(256) impreduce_kernel() {
    int gt = blockIdx.x * 256 + threadIdx.x;
    int b = gt >> 10, t = gt & 1023;
    float s = 0.f;
    const float* p = g_part + (size_t)b * 128 * Tc + t;
    for (int i = 0; i < 128; i++) { s += p[(size_t)i * Tc]; }
    float posn = (float)(Tc - t) / (float)Tc;
    g_imp[gt] = (s / (float)Hc) / (posn + 1e-8f);
}

__global__ void __launch_bounds__(1024) finalize_kernel(const int* __restrict__ amask,
                                                        const float* __restrict__ thrp,
                                                        float* __restrict__ outp) {
    int tid = threadIdx.x;
    float m = -3.4e38f;
    for (int i = tid; i < BT; i += 1024) { m = fmaxf(m, g_imp[i]); }
    __shared__ float red[32];
    #pragma unroll
    for (int o = 16; o; o >>= 1) { m = fmaxf(m, __shfl_xor_sync(~0u, m, o)); }
    if ((tid & 31) == 0) red[tid >> 5] = m;
    __syncthreads();
    if (tid < 32) {
        float v = red[tid];
        #pragma unroll
        for (int o = 16; o; o >>= 1) { v = fmaxf(v, __shfl_xor_sync(~0u, v, o)); }
        if (tid == 0) red[0] = v;
    }
    __syncthreads();
    float maxv = red[0];
    float thr = *thrp;
    float* maskp = outp + (size_t)BT * Cc;
    float* impp  = maskp + BT;
    for (int i = tid; i < BT; i += 1024) {
        int t = i & 1023;
        float iv = g_imp[i];
        if (t < SINKc) iv = maxv + 1.0f;
        float mk = (iv >= thr) ? 1.0f : 0.0f;
        if (t < SINKc) mk = 1.0f;
        if (amask[i] == 0) mk = 0.0f;
        maskp[i] = mk;
        impp[i]  = iv;
    }
}

// ---------------- launch ----------------
extern "C" void kernel_launch(void* const* d_in, const int* in_sizes, int n_in,
                              void* d_out, int out_size) {
    (void)in_sizes; (void)n_in; (void)out_size;
    const float* x      = (const float*)d_in[0];
    const int*   amask  = (const int*)  d_in[1];
    const float* W_attn = (const float*)d_in[2];
    const float* b_attn = (const float*)d_in[3];
    const float* W_proj = (const float*)d_in[4];
    const float* b_proj = (const float*)d_in[5];
    const float* ln1_w  = (const float*)d_in[6];
    const float* ln1_b  = (const float*)d_in[7];
    const float* ln2_w  = (const float*)d_in[8];
    const float* ln2_b  = (const float*)d_in[9];
    const float* W_fc   = (const float*)d_in[10];
    const float* b_fc   = (const float*)d_in[11];
    const float* W_fc2  = (const float*)d_in[12];
    const float* b_fc2  = (const float*)d_in[13];
    const float* thr    = (const float*)d_in[14];
    float* outp = (float*)d_out;

    float *ph, *pq, *pk, *pvt, *py, *pfc, *px2, *pwat, *pwpt, *pwft, *pwf2t;
    cudaGetSymbolAddress((void**)&ph,    g_h);
    cudaGetSymbolAddress((void**)&pq,    g_q);
    cudaGetSymbolAddress((void**)&pk,    g_k);
    cudaGetSymbolAddress((void**)&pvt,   g_vt);
    cudaGetSymbolAddress((void**)&py,    g_y);
    cudaGetSymbolAddress((void**)&pfc,   g_fc);
    cudaGetSymbolAddress((void**)&px2,   g_x2);
    cudaGetSymbolAddress((void**)&pwat,  g_wat);
    cudaGetSymbolAddress((void**)&pwpt,  g_wpt);
    cudaGetSymbolAddress((void**)&pwft,  g_wft);
    cudaGetSymbolAddress((void**)&pwf2t, g_wf2t);

    cudaFuncSetAttribute(mma_gemm<1>, cudaFuncAttributeMaxDynamicSharedMemorySize, GSMEM_BYTES);
    cudaFuncSetAttribute(mma_gemm<2>, cudaFuncAttributeMaxDynamicSharedMemorySize, GSMEM_BYTES);
    cudaFuncSetAttribute(mma_gemm<3>, cudaFuncAttributeMaxDynamicSharedMemorySize, GSMEM_BYTES);
    cudaFuncSetAttribute(flash_kernel, cudaFuncAttributeMaxDynamicSharedMemorySize, ATT_SMEM_BYTES);

    tr_kernel<<<dim3(3*Cc/32, Cc/32),   256>>>(W_attn, pwat,  Cc,   3*Cc);
    tr_kernel<<<dim3(Cc/32,   Cc/32),   256>>>(W_proj, pwpt,  Cc,   Cc);
    tr_kernel<<<dim3(4*Cc/32, Cc/32),   256>>>(W_fc,   pwft,  Cc,   4*Cc);
    tr_kernel<<<dim3(Cc/32,   4*Cc/32), 256>>>(W_fc2,  pwf2t, 4*Cc, Cc);

    ln_kernel<<<BT, 256>>>(x, ln1_w, ln1_b, ph);
    mma_gemm<1><<<dim3(3*Cc/128, BT/128), 256, GSMEM_BYTES>>>(ph, pwat, b_attn, nullptr,
                                                 nullptr, pq, pk, pvt, BT, 3*Cc, Cc);
    flash_kernel<<<dim3(Tc/128, Bc*Hc), 256, ATT_SMEM_BYTES>>>(amask);
    impreduce_kernel<<<16, 256>>>();
    mma_gemm<2><<<dim3(Cc/128, BT/128), 256, GSMEM_BYTES>>>(py, pwpt, b_proj, x,
                                               px2, nullptr, nullptr, nullptr, BT, Cc, Cc);
    ln_kernel<<<BT, 256>>>(px2, ln2_w, ln2_b, ph);
    mma_gemm<3><<<dim3(4*Cc/128, BT/128), 256, GSMEM_BYTES>>>(ph, pwft, b_fc, nullptr,
                                                 pfc, nullptr, nullptr, nullptr, BT, 4*Cc, Cc);
    mma_gemm<2><<<dim3(Cc/128, BT/128), 256, GSMEM_BYTES>>>(pfc, pwf2t, b_fc2, px2,
                                               outp, nullptr, nullptr, nullptr, BT, Cc, 4*Cc);
    finalize_kernel<<<1, 1024>>>(amask, thr, outp);
}

// round 8
// speedup vs baseline: 2.4102x; 1.0248x over previous
#include <cuda_runtime.h>
#include <cuda_bf16.h>
#include <cstdint>
#include <math.h>

#define Bc 4
#define Tc 1024
#define Cc 1024
#define Hc 16
#define Dc 64
#define BT (Bc*Tc)
#define SINKc 4

// ---------------- scratch ----------------
__device__ float g_h  [(size_t)BT*Cc];
__device__ float g_q  [(size_t)BT*Cc];        // (B,H,T,D) tf32-rounded
__device__ float g_k  [(size_t)BT*Cc];
__device__ float g_vt [(size_t)BT*Cc];        // (B,H,D,T)
__device__ float g_y  [(size_t)BT*Cc];        // (B,T,C)
__device__ float g_fc [(size_t)BT*4*Cc];
__device__ float g_x2 [(size_t)BT*Cc];
__device__ float g_part[(size_t)Bc*Hc*8*Tc];
__device__ float g_imp[BT];
__device__ float g_wat [(size_t)3*Cc*Cc];
__device__ float g_wpt [(size_t)Cc*Cc];
__device__ float g_wft [(size_t)4*Cc*Cc];
__device__ float g_wf2t[(size_t)Cc*4*Cc];

// ---------------- helpers ----------------
__device__ __forceinline__ uint32_t smem_u32(const void* p) {
    uint32_t r;
    asm("{ .reg .u64 t; cvta.to.shared.u64 t, %1; cvt.u32.u64 %0, t; }"
        : "=r"(r) : "l"(p));
    return r;
}
__device__ __forceinline__ void ldsm4(uint32_t& r0, uint32_t& r1, uint32_t& r2, uint32_t& r3, uint32_t a) {
    asm volatile("ldmatrix.sync.aligned.m8n8.x4.shared.b16 {%0,%1,%2,%3},[%4];"
        : "=r"(r0), "=r"(r1), "=r"(r2), "=r"(r3) : "r"(a));
}
__device__ __forceinline__ void mma_tf32(float* c, uint32_t a0, uint32_t a1, uint32_t a2, uint32_t a3,
                                         uint32_t b0, uint32_t b1) {
    asm volatile("mma.sync.aligned.m16n8k8.row.col.f32.tf32.tf32.f32 "
        "{%0,%1,%2,%3},{%4,%5,%6,%7},{%8,%9},{%0,%1,%2,%3};"
        : "+f"(c[0]), "+f"(c[1]), "+f"(c[2]), "+f"(c[3])
        : "r"(a0), "r"(a1), "r"(a2), "r"(a3), "r"(b0), "r"(b1));
}
__device__ __forceinline__ uint32_t f2tf(float f) {
    uint32_t u;
    asm("cvt.rna.tf32.f32 %0, %1;" : "=r"(u) : "f"(f));
    return u;
}
__device__ __forceinline__ float rnd(float f) { return __uint_as_float(f2tf(f)); }
__device__ __forceinline__ void cp16(uint32_t s, const void* g) {
    asm volatile("cp.async.cg.shared.global [%0], [%1], 16;" :: "r"(s), "l"(g));
}
#define CP_COMMIT() asm volatile("cp.async.commit_group;")
#define CP_WAIT2()  asm volatile("cp.async.wait_group 2;")

// ---------------- weight transpose (tf32-rounded) ----------------
__global__ void __launch_bounds__(256) tr_kernel(const float* __restrict__ W,
                                                 float* __restrict__ Wt, int K, int N) {
    __shared__ float ts[32][33];
    int k0 = blockIdx.y * 32, n0 = blockIdx.x * 32;
    int tx = threadIdx.x & 31, ty = threadIdx.x >> 5;
    #pragma unroll
    for (int i = 0; i < 4; i++) {
        ts[ty + i*8][tx] = W[(size_t)(k0 + ty + i*8) * N + n0 + tx];
    }
    __syncthreads();
    #pragma unroll
    for (int i = 0; i < 4; i++) {
        Wt[(size_t)(n0 + ty + i*8) * K + k0 + tx] = rnd(ts[tx][ty + i*8]);
    }
}

// ---------------- LayerNorm (tf32-rounded out) ----------------
__global__ void __launch_bounds__(256) ln_kernel(const float* __restrict__ x,
                                                 const float* __restrict__ w,
                                                 const float* __restrict__ b,
                                                 float* __restrict__ out) {
    int row = blockIdx.x;
    int tid = threadIdx.x;
    const float* xr = x + (size_t)row * Cc;
    float4 v = *(const float4*)(xr + tid * 4);
    float s  = v.x + v.y + v.z + v.w;
    float s2 = v.x*v.x + v.y*v.y + v.z*v.z + v.w*v.w;
    #pragma unroll
    for (int o = 16; o; o >>= 1) {
        s  += __shfl_xor_sync(~0u, s,  o);
        s2 += __shfl_xor_sync(~0u, s2, o);
    }
    __shared__ float ws[8], ws2[8];
    int wid = tid >> 5, lid = tid & 31;
    if (lid == 0) { ws[wid] = s; ws2[wid] = s2; }
    __syncthreads();
    if (tid < 8) {
        float a = ws[tid], a2 = ws2[tid];
        #pragma unroll
        for (int o = 4; o; o >>= 1) {
            a  += __shfl_xor_sync(0xffu, a,  o);
            a2 += __shfl_xor_sync(0xffu, a2, o);
        }
        if (tid == 0) { ws[0] = a; ws2[0] = a2; }
    }
    __syncthreads();
    float mean = ws[0] * (1.0f / Cc);
    float var  = ws2[0] * (1.0f / Cc) - mean * mean;
    float inv  = rsqrtf(var + 1e-5f);
    int c = tid * 4;
    float4 wv = *(const float4*)(w + c);
    float4 bv = *(const float4*)(b + c);
    float4 ov;
    ov.x = rnd((v.x - mean) * inv * wv.x + bv.x);
    ov.y = rnd((v.y - mean) * inv * wv.y + bv.y);
    ov.z = rnd((v.z - mean) * inv * wv.z + bv.z);
    ov.w = rnd((v.w - mean) * inv * wv.w + bv.w);
    *(float4*)(out + (size_t)row * Cc + c) = ov;
}

// ---------------- tf32 MMA GEMM, cp.async 4-stage, occupancy 2 ----------------
#define GSTAGES 4
#define GSMEM_BYTES (GSTAGES * 2 * 128 * 20 * 4)
template<int EPI>
__global__ void __launch_bounds__(256, 2) mma_gemm(
    const float* __restrict__ A, const float* __restrict__ Bt,
    const float* __restrict__ bias, const float* __restrict__ res,
    float* __restrict__ outF, float* __restrict__ outQ,
    float* __restrict__ outK, float* __restrict__ outVt,
    int M, int N, int K)
{
    extern __shared__ float dsm[];
    typedef float (*Tile)[128][20];
    Tile As = (Tile)dsm;
    Tile Bs = (Tile)(dsm + GSTAGES * 128 * 20);

    int tid = threadIdx.x, lane = tid & 31, wid = tid >> 5;
    int wm = wid & 3, wn = wid >> 2;
    int bm = blockIdx.y * 128, bn = blockIdx.x * 128;

    float acc[2][8][4];
    #pragma unroll
    for (int i = 0; i < 2; i++) {
        #pragma unroll
        for (int j = 0; j < 8; j++) {
            #pragma unroll
            for (int k = 0; k < 4; k++) { acc[i][j][k] = 0.f; }
        }
    }

    int row = tid >> 1, kc = (tid & 1) * 8;
    const float* Ap = A  + (size_t)(bm + row) * K + kc;
    const float* Bp = Bt + (size_t)(bn + row) * K + kc;

    #pragma unroll
    for (int s = 0; s < GSTAGES - 1; s++) {
        int k0 = s * 16;
        cp16(smem_u32(&As[s][row][kc]),     Ap + k0);
        cp16(smem_u32(&As[s][row][kc + 4]), Ap + k0 + 4);
        cp16(smem_u32(&Bs[s][row][kc]),     Bp + k0);
        cp16(smem_u32(&Bs[s][row][kc + 4]), Bp + k0 + 4);
        CP_COMMIT();
    }

    int nk = K >> 4;
    for (int it = 0; it < nk; it++) {
        CP_WAIT2();
        __syncthreads();
        int st = it & (GSTAGES - 1);
        int nx = it + GSTAGES - 1;
        if (nx < nk) {
            int sx = nx & (GSTAGES - 1);
            int k0 = nx << 4;
            cp16(smem_u32(&As[sx][row][kc]),     Ap + k0);
            cp16(smem_u32(&As[sx][row][kc + 4]), Ap + k0 + 4);
            cp16(smem_u32(&Bs[sx][row][kc]),     Bp + k0);
            cp16(smem_u32(&Bs[sx][row][kc + 4]), Bp + k0 + 4);
        }
        CP_COMMIT();
        #pragma unroll
        for (int kk = 0; kk < 16; kk += 8) {
            uint32_t af[2][4];
            #pragma unroll
            for (int mt = 0; mt < 2; mt++) {
                ldsm4(af[mt][0], af[mt][1], af[mt][2], af[mt][3],
                      smem_u32(&As[st][wm*32 + mt*16 + (lane & 15)][kk + (lane >> 4) * 4]));
            }
            uint32_t bfr[8][2];
            #pragma unroll
            for (int np = 0; np < 4; np++) {
                uint32_t r0, r1, r2, r3;
                ldsm4(r0, r1, r2, r3,
                      smem_u32(&Bs[st][wn*64 + np*16 + (lane & 15)][kk + (lane >> 4) * 4]));
                bfr[np*2][0] = r0;   bfr[np*2][1] = r2;
                bfr[np*2+1][0] = r1; bfr[np*2+1][1] = r3;
            }
            #pragma unroll
            for (int mt = 0; mt < 2; mt++) {
                #pragma unroll
                for (int nt = 0; nt < 8; nt++) {
                    mma_tf32(acc[mt][nt], af[mt][0], af[mt][1], af[mt][2], af[mt][3],
                             bfr[nt][0], bfr[nt][1]);
                }
            }
        }
    }

    #pragma unroll
    for (int mt = 0; mt < 2; mt++) {
        #pragma unroll
        for (int nt = 0; nt < 8; nt++) {
            int r0 = bm + wm*32 + mt*16 + (lane >> 2);
            int c0 = bn + wn*64 + nt*8 + (lane & 3) * 2;
            float bb0 = bias[c0], bb1 = bias[c0 + 1];
            #pragma unroll
            for (int rr = 0; rr < 2; rr++) {
                int rg = r0 + rr * 8;
                float v0 = acc[mt][nt][rr*2 + 0] + bb0;
                float v1 = acc[mt][nt][rr*2 + 1] + bb1;
                if (EPI == 1) {
                    int sec = c0 >> 10, wc = c0 & 1023;
                    int h = wc >> 6, d = wc & 63;
                    int bbi = rg >> 10, t = rg & 1023;
                    if (sec == 0) {
                        float2 o; o.x = rnd(v0); o.y = rnd(v1);
                        *(float2*)&outQ[(((size_t)(bbi*Hc + h))*Tc + t)*Dc + d] = o;
                    } else if (sec == 1) {
                        float2 o; o.x = rnd(v0); o.y = rnd(v1);
                        *(float2*)&outK[(((size_t)(bbi*Hc + h))*Tc + t)*Dc + d] = o;
                    } else {
                        size_t vb = (((size_t)(bbi*Hc + h))*Dc + d)*Tc + t;
                        outVt[vb] = rnd(v0);
                        outVt[vb + Tc] = rnd(v1);
                    }
                } else if (EPI == 2) {
                    size_t idx = (size_t)rg * N + c0;
                    float2 rv = *(const float2*)(res + idx);
                    float2 o; o.x = v0 + rv.x; o.y = v1 + rv.y;
                    *(float2*)(outF + idx) = o;
                } else {
                    float g0 = 0.5f * v0 * (1.0f + erff(v0 * 0.70710678118654752f));
                    float g1 = 0.5f * v1 * (1.0f + erff(v1 * 0.70710678118654752f));
                    float2 o; o.x = rnd(g0); o.y = rnd(g1);
                    *(float2*)&outF[(size_t)rg * N + c0] = o;
                }
            }
        }
    }
}

// ================ fused flash attention (two-pass) ================
#define OFF_QS 0
#define OFF_KS 8704
#define OFF_SS 17408
#define OFF_VS 34304
#define OFF_M  42752
#define OFF_L  42880
#define OFF_MN 43008
#define OFF_RED 43136
#define ATT_SMEM_FLOATS 43392
#define ATT_SMEM_BYTES (ATT_SMEM_FLOATS * 4)

__device__ __forceinline__ void compute_S(
    const float (*Qs)[68], const float (*Ks)[68],
    int wm, int wn, int lane, float acc[2][8][4])
{
    #pragma unroll
    for (int i = 0; i < 2; i++) {
        #pragma unroll
        for (int j = 0; j < 8; j++) {
            #pragma unroll
            for (int k = 0; k < 4; k++) { acc[i][j][k] = 0.f; }
        }
    }
    #pragma unroll
    for (int kk = 0; kk < 64; kk += 8) {
        uint32_t af[2][4];
        #pragma unroll
        for (int mt = 0; mt < 2; mt++) {
            ldsm4(af[mt][0], af[mt][1], af[mt][2], af[mt][3],
                  smem_u32(&Qs[wm*32 + mt*16 + (lane & 15)][kk + (lane >> 4) * 4]));
        }
        uint32_t bfr[8][2];
        #pragma unroll
        for (int np = 0; np < 4; np++) {
            uint32_t r0, r1, r2, r3;
            ldsm4(r0, r1, r2, r3,
                  smem_u32(&Ks[wn*64 + np*16 + (lane & 15)][kk + (lane >> 4) * 4]));
            bfr[np*2][0] = r0;   bfr[np*2][1] = r2;
            bfr[np*2+1][0] = r1; bfr[np*2+1][1] = r3;
        }
        #pragma unroll
        for (int mt = 0; mt < 2; mt++) {
            #pragma unroll
            for (int nt = 0; nt < 8; nt++) {
                mma_tf32(acc[mt][nt], af[mt][0], af[mt][1], af[mt][2], af[mt][3],
                         bfr[nt][0], bfr[nt][1]);
            }
        }
    }
}

__global__ void __launch_bounds__(256, 1) flash_kernel(const int* __restrict__ amask) {
    extern __shared__ float sm[];
    float (*Qs)[68]  = (float(*)[68]) (sm + OFF_QS);
    float (*Ks)[68]  = (float(*)[68]) (sm + OFF_KS);
    float (*Ss)[132] = (float(*)[132])(sm + OFF_SS);
    float (*Vs)[132] = (float(*)[132])(sm + OFF_VS);
    float* m_s  = sm + OFF_M;
    float* l_s  = sm + OFF_L;
    float* mn_s = sm + OFF_MN;
    float* red  = sm + OFF_RED;

    int bh = blockIdx.y, b = bh >> 4, h = bh & 15;
    int qblk = (int)(gridDim.x - 1 - blockIdx.x);
    int i0 = qblk << 7;
    int tid = threadIdx.x, lane = tid & 31, wid = tid >> 5;
    int wm = wid & 3, wn = wid >> 2;

    {
        int row = tid >> 1, c0 = (tid & 1) * 32;
        const float* qp = g_q + ((size_t)bh*Tc + i0 + row)*Dc + c0;
        #pragma unroll
        for (int c4 = 0; c4 < 32; c4 += 4) {
            *(float4*)&Qs[row][c0 + c4] = *(const float4*)(qp + c4);
        }
    }
    if (tid < 128) { m_s[tid] = -3.0e38f; l_s[tid] = 0.f; }
    __syncthreads();

    int nj = qblk + 1;
    float acc[2][8][4];

    for (int jb = 0; jb < nj; jb++) {
        int j0 = jb << 7;
        {
            int row = tid >> 1, c0 = (tid & 1) * 32;
            const float* kp = g_k + ((size_t)bh*Tc + j0 + row)*Dc + c0;
            #pragma unroll
            for (int c4 = 0; c4 < 32; c4 += 4) {
                *(float4*)&Ks[row][c0 + c4] = *(const float4*)(kp + c4);
            }
        }
        __syncthreads();
        compute_S(Qs, Ks, wm, wn, lane, acc);
        #pragma unroll
        for (int mt = 0; mt < 2; mt++) {
            #pragma unroll
            for (int nt = 0; nt < 8; nt++) {
                int c0 = j0 + wn*64 + nt*8 + (lane & 3) * 2;
                int am0 = amask[b*Tc + c0], am1 = amask[b*Tc + c0 + 1];
                #pragma unroll
                for (int rr = 0; rr < 2; rr++) {
                    int r = i0 + wm*32 + mt*16 + rr*8 + (lane >> 2);
                    float s0 = acc[mt][nt][rr*2 + 0] * 0.125f;
                    float s1 = acc[mt][nt][rr*2 + 1] * 0.125f;
                    acc[mt][nt][rr*2 + 0] = (c0     <= r && am0) ? s0 : -1e30f;
                    acc[mt][nt][rr*2 + 1] = (c0 + 1 <= r && am1) ? s1 : -1e30f;
                }
            }
        }
        #pragma unroll
        for (int mt = 0; mt < 2; mt++) {
            #pragma unroll
            for (int rr = 0; rr < 2; rr++) {
                float bmx = -3.4e38f;
                #pragma unroll
                for (int nt = 0; nt < 8; nt++) {
                    bmx = fmaxf(bmx, fmaxf(acc[mt][nt][rr*2], acc[mt][nt][rr*2 + 1]));
                }
                bmx = fmaxf(bmx, __shfl_xor_sync(~0u, bmx, 1));
                bmx = fmaxf(bmx, __shfl_xor_sync(~0u, bmx, 2));
                if ((lane & 3) == 0) {
                    red[wn*128 + wm*32 + mt*16 + rr*8 + (lane >> 2)] = bmx;
                }
            }
        }
        __syncthreads();
        if (wn == 0 && (lane & 3) == 0) {
            #pragma unroll
            for (int mt = 0; mt < 2; mt++) {
                #pragma unroll
                for (int rr = 0; rr < 2; rr++) {
                    int rl = wm*32 + mt*16 + rr*8 + (lane >> 2);
                    mn_s[rl] = fmaxf(m_s[rl], fmaxf(red[rl], red[128 + rl]));
                }
            }
        }
        __syncthreads();
        #pragma unroll
        for (int mt = 0; mt < 2; mt++) {
            #pragma unroll
            for (int rr = 0; rr < 2; rr++) {
                int rl = wm*32 + mt*16 + rr*8 + (lane >> 2);
                float mnew = mn_s[rl];
                float e = 0.f;
                #pragma unroll
                for (int nt = 0; nt < 8; nt++) {
                    e += __expf(acc[mt][nt][rr*2]     - mnew);
                    e += __expf(acc[mt][nt][rr*2 + 1] - mnew);
                }
                e += __shfl_xor_sync(~0u, e, 1);
                e += __shfl_xor_sync(~0u, e, 2);
                if ((lane & 3) == 0) { red[wn*128 + rl] = e; }
            }
        }
        __syncthreads();
        if (wn == 0 && (lane & 3) == 0) {
            #pragma unroll
            for (int mt = 0; mt < 2; mt++) {
                #pragma unroll
                for (int rr = 0; rr < 2; rr++) {
                    int rl = wm*32 + mt*16 + rr*8 + (lane >> 2);
                    float mnew = mn_s[rl];
                    l_s[rl] = l_s[rl] * __expf(m_s[rl] - mnew) + red[rl] + red[128 + rl];
                    m_s[rl] = mnew;
                }
            }
        }
        __syncthreads();
    }
    if (tid < 128) {
        float l = l_s[tid];
        l_s[tid] = (l > 0.f) ? (1.0f / l) : 0.f;
    }
    __syncthreads();

    float acco[8][4];
    #pragma unroll
    for (int j = 0; j < 8; j++) {
        #pragma unroll
        for (int k = 0; k < 4; k++) { acco[j][k] = 0.f; }
    }

    for (int jb = 0; jb < nj; jb++) {
        int j0 = jb << 7;
        {
            int row = tid >> 1, c0 = (tid & 1) * 32;
            const float* kp = g_k + ((size_t)bh*Tc + j0 + row)*Dc + c0;
            #pragma unroll
            for (int c4 = 0; c4 < 32; c4 += 4) {
                *(float4*)&Ks[row][c0 + c4] = *(const float4*)(kp + c4);
            }
            int rowv = tid >> 2, cv0 = (tid & 3) * 32;
            const float* vp = g_vt + ((size_t)bh*Dc + rowv)*Tc + j0 + cv0;
            #pragma unroll
            for (int c4 = 0; c4 < 32; c4 += 4) {
                *(float4*)&Vs[rowv][cv0 + c4] = *(const float4*)(vp + c4);
            }
        }
        __syncthreads();
        compute_S(Qs, Ks, wm, wn, lane, acc);
        #pragma unroll
        for (int mt = 0; mt < 2; mt++) {
            #pragma unroll
            for (int nt = 0; nt < 8; nt++) {
                int cl = wn*64 + nt*8 + (lane & 3) * 2;
                int c0 = j0 + cl;
                int am0 = amask[b*Tc + c0], am1 = amask[b*Tc + c0 + 1];
                #pragma unroll
                for (int rr = 0; rr < 2; rr++) {
                    int rl = wm*32 + mt*16 + rr*8 + (lane >> 2);
                    int r = i0 + rl;
                    float ml = m_s[rl], il = l_s[rl];
                    float s0 = acc[mt][nt][rr*2 + 0] * 0.125f;
                    float s1 = acc[mt][nt][rr*2 + 1] * 0.125f;
                    float p0 = (c0     <= r && am0) ? (__expf(s0 - ml) * il) : 0.f;
                    float p1 = (c0 + 1 <= r && am1) ? (__expf(s1 - ml) * il) : 0.f;
                    float2 pv; pv.x = rnd(p0); pv.y = rnd(p1);
                    *(float2*)&Ss[rl][cl] = pv;
                }
            }
        }
        __syncthreads();
        if (tid < 128) {
            float s = 0.f;
            #pragma unroll 8
            for (int r = 0; r < 128; r++) { s += Ss[r][tid]; }
            g_part[((size_t)bh*8 + qblk)*Tc + j0 + tid] = s;
        }
        #pragma unroll
        for (int kk = 0; kk < 128; kk += 8) {
            uint32_t af[4];
            ldsm4(af[0], af[1], af[2], af[3],
                  smem_u32(&Ss[wid*16 + (lane & 15)][kk + (lane >> 4) * 4]));
            uint32_t bfr[8][2];
            #pragma unroll
            for (int np = 0; np < 4; np++) {
                uint32_t r0, r1, r2, r3;
                ldsm4(r0, r1, r2, r3,
                      smem_u32(&Vs[np*16 + (lane & 15)][kk + (lane >> 4) * 4]));
                bfr[np*2][0] = r0;   bfr[np*2][1] = r2;
                bfr[np*2+1][0] = r1; bfr[np*2+1][1] = r3;
            }
            #pragma unroll
            for (int nt = 0; nt < 8; nt++) {
                mma_tf32(acco[nt], af[0], af[1], af[2], af[3], bfr[nt][0], bfr[nt][1]);
            }
        }
        __syncthreads();
    }

    #pragma unroll
    for (int nt = 0; nt < 8; nt++) {
        int q0 = i0 + wid*16 + (lane >> 2);
        int d0 = nt*8 + (lane & 3) * 2;
        #pragma unroll
        for (int rr = 0; rr < 2; rr++) {
            int q = q0 + rr * 8;
            float2 o; o.x = rnd(acco[nt][rr*2]); o.y = rnd(acco[nt][rr*2 + 1]);
            *(float2*)&g_y[(size_t)(b*Tc + q) * Cc + h*64 + d0] = o;
        }
    }
    for (int c = i0 + 128 + tid; c < Tc; c += 256) {
        g_part[((size_t)bh*8 + qblk)*Tc + c] = 0.f;
    }
}

// ---------------- imp reduce ----------------
__global__ void __launch_bounds__(256) impreduce_kernel() {
    int gt = blockIdx.x * 256 + threadIdx.x;
    int b = gt >> 10, t = gt & 1023;
    float s = 0.f;
    const float* p = g_part + (size_t)b * 128 * Tc + t;
    for (int i = 0; i < 128; i++) { s += p[(size_t)i * Tc]; }
    float posn = (float)(Tc - t) / (float)Tc;
    g_imp[gt] = (s / (float)Hc) / (posn + 1e-8f);
}

__global__ void __launch_bounds__(1024) finalize_kernel(const int* __restrict__ amask,
                                                        const float* __restrict__ thrp,
                                                        float* __restrict__ outp) {
    int tid = threadIdx.x;
    float m = -3.4e38f;
    for (int i = tid; i < BT; i += 1024) { m = fmaxf(m, g_imp[i]); }
    __shared__ float red[32];
    #pragma unroll
    for (int o = 16; o; o >>= 1) { m = fmaxf(m, __shfl_xor_sync(~0u, m, o)); }
    if ((tid & 31) == 0) red[tid >> 5] = m;
    __syncthreads();
    if (tid < 32) {
        float v = red[tid];
        #pragma unroll
        for (int o = 16; o; o >>= 1) { v = fmaxf(v, __shfl_xor_sync(~0u, v, o)); }
        if (tid == 0) red[0] = v;
    }
    __syncthreads();
    float maxv = red[0];
    float thr = *thrp;
    float* maskp = outp + (size_t)BT * Cc;
    float* impp  = maskp + BT;
    for (int i = tid; i < BT; i += 1024) {
        int t = i & 1023;
        float iv = g_imp[i];
        if (t < SINKc) iv = maxv + 1.0f;
        float mk = (iv >= thr) ? 1.0f : 0.0f;
        if (t < SINKc) mk = 1.0f;
        if (amask[i] == 0) mk = 0.0f;
        maskp[i] = mk;
        impp[i]  = iv;
    }
}

// ---------------- launch ----------------
extern "C" void kernel_launch(void* const* d_in, const int* in_sizes, int n_in,
                              void* d_out, int out_size) {
    (void)in_sizes; (void)n_in; (void)out_size;
    const float* x      = (const float*)d_in[0];
    const int*   amask  = (const int*)  d_in[1];
    const float* W_attn = (const float*)d_in[2];
    const float* b_attn = (const float*)d_in[3];
    const float* W_proj = (const float*)d_in[4];
    const float* b_proj = (const float*)d_in[5];
    const float* ln1_w  = (const float*)d_in[6];
    const float* ln1_b  = (const float*)d_in[7];
    const float* ln2_w  = (const float*)d_in[8];
    const float* ln2_b  = (const float*)d_in[9];
    const float* W_fc   = (const float*)d_in[10];
    const float* b_fc   = (const float*)d_in[11];
    const float* W_fc2  = (const float*)d_in[12];
    const float* b_fc2  = (const float*)d_in[13];
    const float* thr    = (const float*)d_in[14];
    float* outp = (float*)d_out;

    float *ph, *pq, *pk, *pvt, *py, *pfc, *px2, *pwat, *pwpt, *pwft, *pwf2t;
    cudaGetSymbolAddress((void**)&ph,    g_h);
    cudaGetSymbolAddress((void**)&pq,    g_q);
    cudaGetSymbolAddress((void**)&pk,    g_k);
    cudaGetSymbolAddress((void**)&pvt,   g_vt);
    cudaGetSymbolAddress((void**)&py,    g_y);
    cudaGetSymbolAddress((void**)&pfc,   g_fc);
    cudaGetSymbolAddress((void**)&px2,   g_x2);
    cudaGetSymbolAddress((void**)&pwat,  g_wat);
    cudaGetSymbolAddress((void**)&pwpt,  g_wpt);
    cudaGetSymbolAddress((void**)&pwft,  g_wft);
    cudaGetSymbolAddress((void**)&pwf2t, g_wf2t);

    cudaFuncSetAttribute(mma_gemm<1>, cudaFuncAttributeMaxDynamicSharedMemorySize, GSMEM_BYTES);
    cudaFuncSetAttribute(mma_gemm<2>, cudaFuncAttributeMaxDynamicSharedMemorySize, GSMEM_BYTES);
    cudaFuncSetAttribute(mma_gemm<3>, cudaFuncAttributeMaxDynamicSharedMemorySize, GSMEM_BYTES);
    cudaFuncSetAttribute(flash_kernel, cudaFuncAttributeMaxDynamicSharedMemorySize, ATT_SMEM_BYTES);

    tr_kernel<<<dim3(3*Cc/32, Cc/32),   256>>>(W_attn, pwat,  Cc,   3*Cc);
    tr_kernel<<<dim3(Cc/32,   Cc/32),   256>>>(W_proj, pwpt,  Cc,   Cc);
    tr_kernel<<<dim3(4*Cc/32, Cc/32),   256>>>(W_fc,   pwft,  Cc,   4*Cc);
    tr_kernel<<<dim3(Cc/32,   4*Cc/32), 256>>>(W_fc2,  pwf2t, 4*Cc, Cc);

    ln_kernel<<<BT, 256>>>(x, ln1_w, ln1_b, ph);
    mma_gemm<1><<<dim3(3*Cc/128, BT/128), 256, GSMEM_BYTES>>>(ph, pwat, b_attn, nullptr,
                                                 nullptr, pq, pk, pvt, BT, 3*Cc, Cc);
    flash_kernel<<<dim3(Tc/128, Bc*Hc), 256, ATT_SMEM_BYTES>>>(amask);
    impreduce_kernel<<<16, 256>>>();
    mma_gemm<2><<<dim3(Cc/128, BT/128), 256, GSMEM_BYTES>>>(py, pwpt, b_proj, x,
                                               px2, nullptr, nullptr, nullptr, BT, Cc, Cc);
    ln_kernel<<<BT, 256>>>(px2, ln2_w, ln2_b, ph);
    mma_gemm<3><<<dim3(4*Cc/128, BT/128), 256, GSMEM_BYTES>>>(ph, pwft, b_fc, nullptr,
                                                 pfc, nullptr, nullptr, nullptr, BT, 4*Cc, Cc);
    mma_gemm<2><<<dim3(Cc/128, BT/128), 256, GSMEM_BYTES>>>(pfc, pwf2t, b_fc2, px2,
                                               outp, nullptr, nullptr, nullptr, BT, Cc, 4*Cc);
    finalize_kernel<<<1, 1024>>>(amask, thr, outp);
}